// round 1
// baseline (speedup 1.0000x reference)
#include <cuda_runtime.h>
#include <cuda_bf16.h>
#include <math_constants.h>

#define B_  4
#define N_  2048
#define C_  768
#define H_  12
#define D_  64
#define M_TOTAL (B_ * N_)        // 8192
#define QKV_COLS (3 * C_)        // 2304

// Scratch (allocation-free rule: __device__ globals)
__device__ float g_q[B_ * H_ * N_ * D_];        // [B,H,N,D]
__device__ float g_k[B_ * H_ * N_ * D_];
__device__ float g_v[B_ * H_ * N_ * D_];
__device__ float g_attout[B_ * N_ * C_];        // [B,N,C]

// ---------------------------------------------------------------------------
// Kernel 1: fused QKV projection.
// Computes x[8192,768] @ [wq | wkv] (+bias) and scatters into g_q/g_k/g_v
// laid out [B,H,N,D]. 64x64 output tile per CTA, BK=16, 256 threads, 4x4
// micro-tile per thread.
// ---------------------------------------------------------------------------
__global__ __launch_bounds__(256) void qkv_gemm_kernel(
    const float* __restrict__ x,
    const float* __restrict__ wq,  const float* __restrict__ bq,
    const float* __restrict__ wkv, const float* __restrict__ bkv)
{
    __shared__ float As[16][64];   // [k][m]
    __shared__ float Bs[16][64];   // [k][n]

    const int row0  = blockIdx.x * 64;
    const int gcol0 = blockIdx.y * 64;

    const int sel = gcol0 / C_;            // 0=q, 1=k, 2=v
    const float* W;
    int ldw, wcol0;
    const float* bias;
    if (sel == 0) { W = wq;  ldw = C_;     wcol0 = gcol0;      bias = bq + gcol0; }
    else          { W = wkv; ldw = 2 * C_; wcol0 = gcol0 - C_; bias = bkv + (gcol0 - C_); }

    const int tid = threadIdx.x;
    const int ty = tid >> 4;       // 0..15
    const int tx = tid & 15;       // 0..15

    float acc[4][4];
#pragma unroll
    for (int i = 0; i < 4; i++)
#pragma unroll
        for (int j = 0; j < 4; j++) acc[i][j] = 0.f;

    const int am = tid >> 2;            // 0..63
    const int ak = (tid & 3) * 4;       // 0,4,8,12
    const int bk = tid >> 4;            // 0..15
    const int bn = (tid & 15) * 4;      // 0..60

    for (int k0 = 0; k0 < C_; k0 += 16) {
        float4 av = *(const float4*)&x[(size_t)(row0 + am) * C_ + k0 + ak];
        As[ak + 0][am] = av.x;
        As[ak + 1][am] = av.y;
        As[ak + 2][am] = av.z;
        As[ak + 3][am] = av.w;
        *(float4*)&Bs[bk][bn] = *(const float4*)&W[(size_t)(k0 + bk) * ldw + wcol0 + bn];
        __syncthreads();
#pragma unroll
        for (int kk = 0; kk < 16; kk++) {
            float a[4], b[4];
            *(float4*)a = *(const float4*)&As[kk][ty * 4];
            *(float4*)b = *(const float4*)&Bs[kk][tx * 4];
#pragma unroll
            for (int i = 0; i < 4; i++)
#pragma unroll
                for (int j = 0; j < 4; j++) acc[i][j] += a[i] * b[j];
        }
        __syncthreads();
    }

    // Epilogue: add bias, scatter into [B,H,N,D]
    const int h = (gcol0 % C_) / D_;
    float* dst_base = (sel == 0) ? g_q : (sel == 1) ? g_k : g_v;
    float bv[4];
    *(float4*)bv = *(const float4*)&bias[tx * 4];

#pragma unroll
    for (int i = 0; i < 4; i++) {
        int grow = row0 + ty * 4 + i;
        int b = grow >> 11;           // / 2048
        int n = grow & (N_ - 1);
        float4 o;
        o.x = acc[i][0] + bv[0];
        o.y = acc[i][1] + bv[1];
        o.z = acc[i][2] + bv[2];
        o.w = acc[i][3] + bv[3];
        *(float4*)&dst_base[(size_t)((b * H_ + h) * N_ + n) * D_ + tx * 4] = o;
    }
}

// ---------------------------------------------------------------------------
// Kernel 2: flash attention.
// One CTA per (b, h, 64-row q tile). Online softmax over 32 key tiles of 64.
// 256 threads; each thread owns a 4x4 tile of S/P and a 4x4 tile of O.
// smem: Qs, Ks, Vs, Ps each 64x68 fp32 (padded) = 69632 B dynamic.
// ---------------------------------------------------------------------------
#define PAD_ 68
#define SMEM_ATTN (4 * 64 * PAD_ * (int)sizeof(float))

__global__ __launch_bounds__(256) void attn_kernel()
{
    extern __shared__ float sm[];
    float* Qs = sm;
    float* Ks = sm + 64 * PAD_;
    float* Vs = sm + 2 * 64 * PAD_;
    float* Ps = sm + 3 * 64 * PAD_;

    const int qt = blockIdx.x;
    const int h  = blockIdx.y;
    const int b  = blockIdx.z;
    const int tid = threadIdx.x;
    const int ty = tid >> 4;
    const int tx = tid & 15;

    const float scale = 0.125f;   // D^-0.5 = 64^-0.5

    const float* qbase = g_q + (size_t)((b * H_ + h) * N_ + qt * 64) * D_;
    const float* kbase = g_k + (size_t)(b * H_ + h) * N_ * D_;
    const float* vbase = g_v + (size_t)(b * H_ + h) * N_ * D_;

    // Load Q tile, folding in scale
    for (int it = tid; it < 64 * 16; it += 256) {
        int off = it * 4;
        int r = off >> 6, c = off & 63;
        float4 v = *(const float4*)(qbase + off);
        v.x *= scale; v.y *= scale; v.z *= scale; v.w *= scale;
        *(float4*)&Qs[r * PAD_ + c] = v;
    }

    float m_i[4], l_i[4], o[4][4];
#pragma unroll
    for (int i = 0; i < 4; i++) {
        m_i[i] = -CUDART_INF_F;
        l_i[i] = 0.f;
#pragma unroll
        for (int j = 0; j < 4; j++) o[i][j] = 0.f;
    }

    for (int kt = 0; kt < N_ / 64; kt++) {
        __syncthreads();   // previous iter's Ks/Vs/Ps fully consumed
        const float* kt_g = kbase + (size_t)kt * 64 * D_;
        const float* vt_g = vbase + (size_t)kt * 64 * D_;
        for (int it = tid; it < 64 * 16; it += 256) {
            int off = it * 4;
            int r = off >> 6, c = off & 63;
            *(float4*)&Ks[r * PAD_ + c] = *(const float4*)(kt_g + off);
            *(float4*)&Vs[r * PAD_ + c] = *(const float4*)(vt_g + off);
        }
        __syncthreads();

        // S = Q K^T (scaled already)
        float s[4][4];
#pragma unroll
        for (int i = 0; i < 4; i++)
#pragma unroll
            for (int j = 0; j < 4; j++) s[i][j] = 0.f;

#pragma unroll 4
        for (int d4 = 0; d4 < 16; d4++) {
            float qv[4][4], kv[4][4];
#pragma unroll
            for (int i = 0; i < 4; i++)
                *(float4*)qv[i] = *(const float4*)&Qs[(ty * 4 + i) * PAD_ + d4 * 4];
#pragma unroll
            for (int j = 0; j < 4; j++)
                *(float4*)kv[j] = *(const float4*)&Ks[(tx * 4 + j) * PAD_ + d4 * 4];
#pragma unroll
            for (int i = 0; i < 4; i++)
#pragma unroll
                for (int j = 0; j < 4; j++)
#pragma unroll
                    for (int c = 0; c < 4; c++)
                        s[i][j] += qv[i][c] * kv[j][c];
        }

        // Online softmax update per row
#pragma unroll
        for (int i = 0; i < 4; i++) {
            float lm = fmaxf(fmaxf(s[i][0], s[i][1]), fmaxf(s[i][2], s[i][3]));
#pragma unroll
            for (int off = 8; off; off >>= 1)
                lm = fmaxf(lm, __shfl_xor_sync(0xFFFFFFFFu, lm, off, 16));
            float mn = fmaxf(m_i[i], lm);
            float alpha = __expf(m_i[i] - mn);
            float ls = 0.f;
#pragma unroll
            for (int j = 0; j < 4; j++) {
                s[i][j] = __expf(s[i][j] - mn);
                ls += s[i][j];
            }
#pragma unroll
            for (int off = 8; off; off >>= 1)
                ls += __shfl_xor_sync(0xFFFFFFFFu, ls, off, 16);
            l_i[i] = l_i[i] * alpha + ls;
            m_i[i] = mn;
#pragma unroll
            for (int j = 0; j < 4; j++) o[i][j] *= alpha;
            // stash P row chunk
            *(float4*)&Ps[(ty * 4 + i) * PAD_ + tx * 4] = *(float4*)s[i];
        }
        __syncthreads();

        // O += P @ V
#pragma unroll 4
        for (int c4 = 0; c4 < 16; c4++) {
            float pv[4][4], vv[4][4];
#pragma unroll
            for (int i = 0; i < 4; i++)
                *(float4*)pv[i] = *(const float4*)&Ps[(ty * 4 + i) * PAD_ + c4 * 4];
#pragma unroll
            for (int cc = 0; cc < 4; cc++)
                *(float4*)vv[cc] = *(const float4*)&Vs[(c4 * 4 + cc) * PAD_ + tx * 4];
#pragma unroll
            for (int i = 0; i < 4; i++)
#pragma unroll
                for (int cc = 0; cc < 4; cc++)
#pragma unroll
                    for (int j = 0; j < 4; j++)
                        o[i][j] += pv[i][cc] * vv[cc][j];
        }
    }

    // Epilogue: normalize, write to g_attout [B,N,C] with C = H*D
#pragma unroll
    for (int i = 0; i < 4; i++) {
        float inv = 1.f / l_i[i];
        int n = qt * 64 + ty * 4 + i;
        float4 ov;
        ov.x = o[i][0] * inv;
        ov.y = o[i][1] * inv;
        ov.z = o[i][2] * inv;
        ov.w = o[i][3] * inv;
        *(float4*)&g_attout[(size_t)(b * N_ + n) * C_ + h * D_ + tx * 4] = ov;
    }
}

// ---------------------------------------------------------------------------
// Kernel 3: output projection: g_attout[8192,768] @ wp[768,768] + bp
// ---------------------------------------------------------------------------
__global__ __launch_bounds__(256) void proj_gemm_kernel(
    const float* __restrict__ wp, const float* __restrict__ bp,
    float* __restrict__ out)
{
    __shared__ float As[16][64];
    __shared__ float Bs[16][64];

    const int row0 = blockIdx.x * 64;
    const int col0 = blockIdx.y * 64;
    const int tid = threadIdx.x;
    const int ty = tid >> 4;
    const int tx = tid & 15;

    float acc[4][4];
#pragma unroll
    for (int i = 0; i < 4; i++)
#pragma unroll
        for (int j = 0; j < 4; j++) acc[i][j] = 0.f;

    const int am = tid >> 2;
    const int ak = (tid & 3) * 4;
    const int bk = tid >> 4;
    const int bn = (tid & 15) * 4;

    for (int k0 = 0; k0 < C_; k0 += 16) {
        float4 av = *(const float4*)&g_attout[(size_t)(row0 + am) * C_ + k0 + ak];
        As[ak + 0][am] = av.x;
        As[ak + 1][am] = av.y;
        As[ak + 2][am] = av.z;
        As[ak + 3][am] = av.w;
        *(float4*)&Bs[bk][bn] = *(const float4*)&wp[(size_t)(k0 + bk) * C_ + col0 + bn];
        __syncthreads();
#pragma unroll
        for (int kk = 0; kk < 16; kk++) {
            float a[4], b[4];
            *(float4*)a = *(const float4*)&As[kk][ty * 4];
            *(float4*)b = *(const float4*)&Bs[kk][tx * 4];
#pragma unroll
            for (int i = 0; i < 4; i++)
#pragma unroll
                for (int j = 0; j < 4; j++) acc[i][j] += a[i] * b[j];
        }
        __syncthreads();
    }

    float bv[4];
    *(float4*)bv = *(const float4*)&bp[col0 + tx * 4];
#pragma unroll
    for (int i = 0; i < 4; i++) {
        int grow = row0 + ty * 4 + i;
        float4 ov;
        ov.x = acc[i][0] + bv[0];
        ov.y = acc[i][1] + bv[1];
        ov.z = acc[i][2] + bv[2];
        ov.w = acc[i][3] + bv[3];
        *(float4*)&out[(size_t)grow * C_ + col0 + tx * 4] = ov;
    }
}

// ---------------------------------------------------------------------------
extern "C" void kernel_launch(void* const* d_in, const int* in_sizes, int n_in,
                              void* d_out, int out_size)
{
    const float* x   = (const float*)d_in[0];
    const float* wq  = (const float*)d_in[1];
    const float* bq  = (const float*)d_in[2];
    const float* wkv = (const float*)d_in[3];
    const float* bkv = (const float*)d_in[4];
    const float* wp  = (const float*)d_in[5];
    const float* bp  = (const float*)d_in[6];
    float* out = (float*)d_out;

    cudaFuncSetAttribute(attn_kernel,
                         cudaFuncAttributeMaxDynamicSharedMemorySize, SMEM_ATTN);

    dim3 g1(M_TOTAL / 64, QKV_COLS / 64);
    qkv_gemm_kernel<<<g1, 256>>>(x, wq, bq, wkv, bkv);

    dim3 g2(N_ / 64, H_, B_);
    attn_kernel<<<g2, 256, SMEM_ATTN>>>();

    dim3 g3(M_TOTAL / 64, C_ / 64);
    proj_gemm_kernel<<<g3, 256>>>(wp, bp, out);
}

// round 3
// speedup vs baseline: 8.4788x; 8.4788x over previous
#include <cuda_runtime.h>
#include <cuda_fp16.h>
#include <math_constants.h>
#include <cstdint>

#define B_  4
#define N_  2048
#define C_  768
#define H_  12
#define D_  64
#define M_TOTAL (B_ * N_)        // 8192

// ---------------------------------------------------------------------------
// Scratch (__device__ globals; allocation-free rule)
// ---------------------------------------------------------------------------
__device__ __half g_xh[M_TOTAL * C_];            // x in fp16 [8192][768]
__device__ __half g_wqkvT[3 * C_ * C_];          // [2304][768] rows: q|k|v, K-major
__device__ __half g_wpT[C_ * C_];                // [768][768]
__device__ __half g_q[B_ * H_ * N_ * D_];        // [B,H,N,D] fp16 (pre-scaled)
__device__ __half g_k[B_ * H_ * N_ * D_];
__device__ __half g_v[B_ * H_ * N_ * D_];
__device__ __half g_attout[M_TOTAL * C_];        // [B,N,C] fp16

// ---------------------------------------------------------------------------
// mma / ldmatrix helpers
// ---------------------------------------------------------------------------
__device__ __forceinline__ uint32_t sptr(const void* p) {
    return (uint32_t)__cvta_generic_to_shared(p);
}

__device__ __forceinline__ void ldm_x4(uint32_t& r0, uint32_t& r1, uint32_t& r2,
                                       uint32_t& r3, uint32_t addr) {
    asm volatile("ldmatrix.sync.aligned.m8n8.x4.shared.b16 {%0,%1,%2,%3}, [%4];"
                 : "=r"(r0), "=r"(r1), "=r"(r2), "=r"(r3) : "r"(addr));
}

__device__ __forceinline__ void ldm_x4_t(uint32_t& r0, uint32_t& r1, uint32_t& r2,
                                         uint32_t& r3, uint32_t addr) {
    asm volatile("ldmatrix.sync.aligned.m8n8.x4.trans.shared.b16 {%0,%1,%2,%3}, [%4];"
                 : "=r"(r0), "=r"(r1), "=r"(r2), "=r"(r3) : "r"(addr));
}

__device__ __forceinline__ void mma16816(float* c,
                                         uint32_t a0, uint32_t a1, uint32_t a2, uint32_t a3,
                                         uint32_t b0, uint32_t b1) {
    asm volatile(
        "mma.sync.aligned.m16n8k16.row.col.f32.f16.f16.f32 "
        "{%0,%1,%2,%3}, {%4,%5,%6,%7}, {%8,%9}, {%0,%1,%2,%3};"
        : "+f"(c[0]), "+f"(c[1]), "+f"(c[2]), "+f"(c[3])
        : "r"(a0), "r"(a1), "r"(a2), "r"(a3), "r"(b0), "r"(b1));
}

// ---------------------------------------------------------------------------
// fp32 -> fp16 convert (n multiple of 4)
// ---------------------------------------------------------------------------
__global__ void f2h_kernel(const float* __restrict__ src, __half* __restrict__ dst, int n)
{
    int i = (blockIdx.x * blockDim.x + threadIdx.x) * 4;
    if (i < n) {
        float4 v = *(const float4*)(src + i);
        *(__half2*)(dst + i)     = __floats2half2_rn(v.x, v.y);
        *(__half2*)(dst + i + 2) = __floats2half2_rn(v.z, v.w);
    }
}

// ---------------------------------------------------------------------------
// fp32 [K][N] -> fp16 [n][k] transpose
// ---------------------------------------------------------------------------
__global__ void transpose_h(const float* __restrict__ src, __half* __restrict__ dst,
                            int K, int N)
{
    __shared__ float t[32][33];
    const int k0 = blockIdx.y * 32;
    const int n0 = blockIdx.x * 32;
    const int tx = threadIdx.x;
    const int ty = threadIdx.y;
#pragma unroll
    for (int i = ty; i < 32; i += 8)
        t[i][tx] = src[(size_t)(k0 + i) * N + n0 + tx];
    __syncthreads();
#pragma unroll
    for (int i = ty; i < 32; i += 8)
        dst[(size_t)(n0 + i) * K + k0 + tx] = __float2half(t[tx][i]);
}

// ---------------------------------------------------------------------------
// hgemm: C[128,128] tile = A[128xK] * Bt[128xK]^T  (K=768, fp16 in, fp32 acc)
//   MODE 0: qkv projection -> scatter fp16 into g_q/g_k/g_v (+bias, q scaled)
//   MODE 1: output projection -> fp32 out (+bias)
// 8 warps: warp grid 4(m) x 2(n), warp tile 32x64.
// smem rows padded to 40 halves (80B) -> conflict-free ldmatrix.
// ---------------------------------------------------------------------------
#define AST 40

template <int MODE>
__global__ __launch_bounds__(256) void hgemm(
    const __half* __restrict__ A, const __half* __restrict__ Bt,
    const float* __restrict__ bq, const float* __restrict__ bkv,
    float* __restrict__ outp)
{
    __shared__ __align__(16) __half As[2][128 * AST];
    __shared__ __align__(16) __half Bs[2][128 * AST];

    const int tid = threadIdx.x;
    const int lane = tid & 31;
    const int wid = tid >> 5;
    const int wm = (wid >> 1) * 32;      // 0,32,64,96
    const int wn = (wid & 1) * 64;       // 0,64
    const int row0 = blockIdx.x * 128;
    const int n0   = blockIdx.y * 128;

    const __half* Ab = A  + (size_t)row0 * C_;
    const __half* Bb = Bt + (size_t)n0   * C_;

    float acc[2][8][4];
#pragma unroll
    for (int i = 0; i < 2; i++)
#pragma unroll
        for (int j = 0; j < 8; j++)
#pragma unroll
            for (int q = 0; q < 4; q++) acc[i][j][q] = 0.f;

    // per-thread global/smem chunk mapping: 512 16B-chunks per tile, 2 per thread
    const int r0c = (tid * 2) >> 2;          // row of chunk pair base
    const int q0c = (tid * 2) & 3;           // 16B chunk within row (0..3)
    // (chunks tid*2, tid*2+1 are consecutive: same row, q0c and q0c+1 since q0c is even)

    uint4 ra[2], rb[2];
    // prologue: load chunk 0 into smem buf 0
#pragma unroll
    for (int i = 0; i < 2; i++) {
        ra[i] = *(const uint4*)(Ab + (size_t)r0c * C_ + 0 + (q0c + i) * 8);
        rb[i] = *(const uint4*)(Bb + (size_t)r0c * C_ + 0 + (q0c + i) * 8);
    }
#pragma unroll
    for (int i = 0; i < 2; i++) {
        *(uint4*)(&As[0][r0c * AST + (q0c + i) * 8]) = ra[i];
        *(uint4*)(&Bs[0][r0c * AST + (q0c + i) * 8]) = rb[i];
    }
    __syncthreads();

    for (int c = 0; c < 24; c++) {
        const int buf = c & 1;
        if (c < 23) {
            const int k0 = (c + 1) * 32;
#pragma unroll
            for (int i = 0; i < 2; i++) {
                ra[i] = *(const uint4*)(Ab + (size_t)r0c * C_ + k0 + (q0c + i) * 8);
                rb[i] = *(const uint4*)(Bb + (size_t)r0c * C_ + k0 + (q0c + i) * 8);
            }
        }
        // compute on buf
#pragma unroll
        for (int kk = 0; kk < 2; kk++) {
            uint32_t a[2][4];
#pragma unroll
            for (int i = 0; i < 2; i++) {
                int row = wm + i * 16 + (lane & 15);
                int col = kk * 16 + ((lane >> 4) << 3);
                ldm_x4(a[i][0], a[i][1], a[i][2], a[i][3],
                       sptr(&As[buf][row * AST + col]));
            }
            uint32_t b[4][4];
#pragma unroll
            for (int p = 0; p < 4; p++) {
                int row = wn + p * 16 + ((lane >> 4) << 3) + (lane & 7);
                int col = kk * 16 + (((lane >> 3) & 1) << 3);
                ldm_x4(b[p][0], b[p][1], b[p][2], b[p][3],
                       sptr(&Bs[buf][row * AST + col]));
            }
#pragma unroll
            for (int i = 0; i < 2; i++)
#pragma unroll
                for (int j = 0; j < 8; j++) {
                    const uint32_t* bp = b[j >> 1];
                    mma16816(acc[i][j], a[i][0], a[i][1], a[i][2], a[i][3],
                             bp[(j & 1) * 2], bp[(j & 1) * 2 + 1]);
                }
        }
        if (c < 23) {
            const int nb = (c + 1) & 1;
#pragma unroll
            for (int i = 0; i < 2; i++) {
                *(uint4*)(&As[nb][r0c * AST + (q0c + i) * 8]) = ra[i];
                *(uint4*)(&Bs[nb][r0c * AST + (q0c + i) * 8]) = rb[i];
            }
            __syncthreads();
        }
    }

    // ------------------------- epilogue -------------------------
    const int gcol0 = n0 + wn;                   // warp col base (mult of 64)
    if (MODE == 0) {
        const int sel = gcol0 / C_;              // whole CTA same sel (128 | 768)
        const float* bias = (sel == 0) ? (bq + gcol0) : (bkv + gcol0 - C_);
        __half* dstb = (sel == 0) ? g_q : (sel == 1) ? g_k : g_v;
        const int h = (gcol0 % C_) / D_;         // warp-constant
        const float qs = (sel == 0) ? 0.125f : 1.0f;
#pragma unroll
        for (int i = 0; i < 2; i++) {
            int mlow = row0 + wm + i * 16 + (lane >> 2);
#pragma unroll
            for (int rh = 0; rh < 2; rh++) {
                int m = mlow + rh * 8;
                int bb = m >> 11;
                int nn = m & (N_ - 1);
                __half* drow = dstb + (size_t)((bb * H_ + h) * N_ + nn) * D_;
#pragma unroll
                for (int j = 0; j < 8; j++) {
                    int d = j * 8 + 2 * (lane & 3);
                    float2 bv = *(const float2*)(bias + j * 8 + 2 * (lane & 3));
                    float v0 = (acc[i][j][rh * 2 + 0] + bv.x) * qs;
                    float v1 = (acc[i][j][rh * 2 + 1] + bv.y) * qs;
                    *(__half2*)(drow + d) = __floats2half2_rn(v0, v1);
                }
            }
        }
    } else {
#pragma unroll
        for (int i = 0; i < 2; i++) {
            int mlow = row0 + wm + i * 16 + (lane >> 2);
#pragma unroll
            for (int rh = 0; rh < 2; rh++) {
                int m = mlow + rh * 8;
                float* orow = outp + (size_t)m * C_ + gcol0;
#pragma unroll
                for (int j = 0; j < 8; j++) {
                    int d = j * 8 + 2 * (lane & 3);
                    float2 bv = *(const float2*)(bq + gcol0 + d);
                    float2 o;
                    o.x = acc[i][j][rh * 2 + 0] + bv.x;
                    o.y = acc[i][j][rh * 2 + 1] + bv.y;
                    *(float2*)(orow + d) = o;
                }
            }
        }
    }
}

// ---------------------------------------------------------------------------
// Flash attention on mma.sync. CTA: 128 q rows of one (b,h); 8 warps x 16 rows.
// KV tiles of 64. Q fragments register-resident. P passes acc->A in registers.
// ---------------------------------------------------------------------------
#define QST 72   // smem row stride (halves) for conflict-free ldmatrix

__global__ __launch_bounds__(256) void attn_kernel()
{
    __shared__ __align__(16) __half Qs[128 * QST];
    __shared__ __align__(16) __half Ks[64 * QST];
    __shared__ __align__(16) __half Vs[64 * QST];

    const int qt = blockIdx.x;
    const int h  = blockIdx.y;
    const int b  = blockIdx.z;
    const int tid = threadIdx.x;
    const int lane = tid & 31;
    const int w = tid >> 5;

    const __half* qbase = g_q + (size_t)((b * H_ + h) * N_ + qt * 128) * D_;
    const __half* kbase = g_k + (size_t)(b * H_ + h) * N_ * D_;
    const __half* vbase = g_v + (size_t)(b * H_ + h) * N_ * D_;

    // load Q tile: 128 rows x 8 16B-chunks = 1024 chunks, 4 per thread
#pragma unroll
    for (int i = 0; i < 4; i++) {
        int cch = tid + 256 * i;
        int r = cch >> 3, q = cch & 7;
        *(uint4*)(&Qs[r * QST + q * 8]) = *(const uint4*)(qbase + (size_t)r * D_ + q * 8);
    }
    __syncthreads();

    // Q fragments: 4 k-steps, register-resident for whole kernel
    uint32_t qa[4][4];
#pragma unroll
    for (int kk = 0; kk < 4; kk++) {
        int row = w * 16 + (lane & 15);
        int col = kk * 16 + ((lane >> 4) << 3);
        ldm_x4(qa[kk][0], qa[kk][1], qa[kk][2], qa[kk][3],
               sptr(&Qs[row * QST + col]));
    }

    float m0 = -CUDART_INF_F, m1 = -CUDART_INF_F;
    float l0 = 0.f, l1 = 0.f;
    float o[8][4];
#pragma unroll
    for (int j = 0; j < 8; j++)
#pragma unroll
        for (int q = 0; q < 4; q++) o[j][q] = 0.f;

    for (int kt = 0; kt < N_ / 64; kt++) {
        const __half* kg = kbase + (size_t)kt * 64 * D_;
        const __half* vg = vbase + (size_t)kt * 64 * D_;
        uint4 rk[2], rv[2];
#pragma unroll
        for (int i = 0; i < 2; i++) {
            int cch = tid + 256 * i;
            int r = cch >> 3, q = cch & 7;
            rk[i] = *(const uint4*)(kg + (size_t)r * D_ + q * 8);
            rv[i] = *(const uint4*)(vg + (size_t)r * D_ + q * 8);
        }
        __syncthreads();     // previous compute done with Ks/Vs
#pragma unroll
        for (int i = 0; i < 2; i++) {
            int cch = tid + 256 * i;
            int r = cch >> 3, q = cch & 7;
            *(uint4*)(&Ks[r * QST + q * 8]) = rk[i];
            *(uint4*)(&Vs[r * QST + q * 8]) = rv[i];
        }
        __syncthreads();

        // S = Q K^T : 8 n-tiles (64 kv) x 4 k-steps
        float s[8][4];
#pragma unroll
        for (int j = 0; j < 8; j++)
#pragma unroll
            for (int q = 0; q < 4; q++) s[j][q] = 0.f;

#pragma unroll
        for (int kk = 0; kk < 4; kk++) {
            uint32_t kb[4][4];
#pragma unroll
            for (int p = 0; p < 4; p++) {
                int row = p * 16 + ((lane >> 4) << 3) + (lane & 7);
                int col = kk * 16 + (((lane >> 3) & 1) << 3);
                ldm_x4(kb[p][0], kb[p][1], kb[p][2], kb[p][3],
                       sptr(&Ks[row * QST + col]));
            }
#pragma unroll
            for (int j = 0; j < 8; j++) {
                const uint32_t* bp = kb[j >> 1];
                mma16816(s[j], qa[kk][0], qa[kk][1], qa[kk][2], qa[kk][3],
                         bp[(j & 1) * 2], bp[(j & 1) * 2 + 1]);
            }
        }

        // online softmax (rows lane>>2 and lane>>2 + 8)
        float mx0 = -CUDART_INF_F, mx1 = -CUDART_INF_F;
#pragma unroll
        for (int j = 0; j < 8; j++) {
            mx0 = fmaxf(mx0, fmaxf(s[j][0], s[j][1]));
            mx1 = fmaxf(mx1, fmaxf(s[j][2], s[j][3]));
        }
        mx0 = fmaxf(mx0, __shfl_xor_sync(0xFFFFFFFFu, mx0, 1));
        mx0 = fmaxf(mx0, __shfl_xor_sync(0xFFFFFFFFu, mx0, 2));
        mx1 = fmaxf(mx1, __shfl_xor_sync(0xFFFFFFFFu, mx1, 1));
        mx1 = fmaxf(mx1, __shfl_xor_sync(0xFFFFFFFFu, mx1, 2));

        float nm0 = fmaxf(m0, mx0), nm1 = fmaxf(m1, mx1);
        float al0 = __expf(m0 - nm0), al1 = __expf(m1 - nm1);
        float sum0 = 0.f, sum1 = 0.f;
        __half2 pl[8], ph[8];
#pragma unroll
        for (int j = 0; j < 8; j++) {
            float e0 = __expf(s[j][0] - nm0);
            float e1 = __expf(s[j][1] - nm0);
            float e2 = __expf(s[j][2] - nm1);
            float e3 = __expf(s[j][3] - nm1);
            sum0 += e0 + e1;
            sum1 += e2 + e3;
            pl[j] = __floats2half2_rn(e0, e1);
            ph[j] = __floats2half2_rn(e2, e3);
        }
        sum0 += __shfl_xor_sync(0xFFFFFFFFu, sum0, 1);
        sum0 += __shfl_xor_sync(0xFFFFFFFFu, sum0, 2);
        sum1 += __shfl_xor_sync(0xFFFFFFFFu, sum1, 1);
        sum1 += __shfl_xor_sync(0xFFFFFFFFu, sum1, 2);

        l0 = l0 * al0 + sum0;
        l1 = l1 * al1 + sum1;
        m0 = nm0; m1 = nm1;
#pragma unroll
        for (int j = 0; j < 8; j++) {
            o[j][0] *= al0; o[j][1] *= al0;
            o[j][2] *= al1; o[j][3] *= al1;
        }

        // O += P V : 4 k-steps (kv) x 8 d-tiles
#pragma unroll
        for (int t = 0; t < 4; t++) {
            uint32_t a0 = *(const uint32_t*)&pl[2 * t];
            uint32_t a1 = *(const uint32_t*)&ph[2 * t];
            uint32_t a2 = *(const uint32_t*)&pl[2 * t + 1];
            uint32_t a3 = *(const uint32_t*)&ph[2 * t + 1];
#pragma unroll
            for (int jd = 0; jd < 4; jd++) {
                uint32_t v0, v1, v2, v3;
                int row = t * 16 + (lane & 15);
                int col = jd * 16 + ((lane >> 4) << 3);
                ldm_x4_t(v0, v1, v2, v3, sptr(&Vs[row * QST + col]));
                mma16816(o[2 * jd],     a0, a1, a2, a3, v0, v1);
                mma16816(o[2 * jd + 1], a0, a1, a2, a3, v2, v3);
            }
        }
    }

    // epilogue: normalize, write fp16 to g_attout [B,N,C]
    float inv0 = 1.f / l0, inv1 = 1.f / l1;
    int nlow = qt * 128 + w * 16 + (lane >> 2);
#pragma unroll
    for (int rh = 0; rh < 2; rh++) {
        int n = nlow + rh * 8;
        __half* drow = g_attout + (size_t)(b * N_ + n) * C_ + h * D_;
        float inv = rh ? inv1 : inv0;
#pragma unroll
        for (int j = 0; j < 8; j++) {
            int d = j * 8 + 2 * (lane & 3);
            *(__half2*)(drow + d) =
                __floats2half2_rn(o[j][rh * 2 + 0] * inv, o[j][rh * 2 + 1] * inv);
        }
    }
}

// ---------------------------------------------------------------------------
extern "C" void kernel_launch(void* const* d_in, const int* in_sizes, int n_in,
                              void* d_out, int out_size)
{
    const float* x   = (const float*)d_in[0];
    const float* wq  = (const float*)d_in[1];
    const float* bq  = (const float*)d_in[2];
    const float* wkv = (const float*)d_in[3];
    const float* bkv = (const float*)d_in[4];
    const float* wp  = (const float*)d_in[5];
    const float* bp  = (const float*)d_in[6];
    float* out = (float*)d_out;

    __half *xh, *wqkvT, *wpT, *attout;
    cudaGetSymbolAddress((void**)&xh,     g_xh);
    cudaGetSymbolAddress((void**)&wqkvT,  g_wqkvT);
    cudaGetSymbolAddress((void**)&wpT,    g_wpT);
    cudaGetSymbolAddress((void**)&attout, g_attout);

    // converts + transposes
    f2h_kernel<<<(M_TOTAL * C_ / 4 + 255) / 256, 256>>>(x, xh, M_TOTAL * C_);
    transpose_h<<<dim3(C_ / 32, C_ / 32), dim3(32, 8)>>>(wq, wqkvT, C_, C_);
    transpose_h<<<dim3(2 * C_ / 32, C_ / 32), dim3(32, 8)>>>(wkv, wqkvT + (size_t)C_ * C_, C_, 2 * C_);
    transpose_h<<<dim3(C_ / 32, C_ / 32), dim3(32, 8)>>>(wp, wpT, C_, C_);

    // QKV projection -> g_q/g_k/g_v (fp16, q pre-scaled)
    hgemm<0><<<dim3(M_TOTAL / 128, (3 * C_) / 128), 256>>>(xh, wqkvT, bq, bkv, nullptr);

    // flash attention -> g_attout (fp16)
    attn_kernel<<<dim3(N_ / 128, H_, B_), 256>>>();

    // output projection -> out (fp32)
    hgemm<1><<<dim3(M_TOTAL / 128, C_ / 128), 256>>>(attout, wpT, bp, nullptr, out);
}

// round 4
// speedup vs baseline: 8.7237x; 1.0289x over previous
#include <cuda_runtime.h>
#include <cuda_fp16.h>
#include <math_constants.h>
#include <cstdint>

#define B_  4
#define N_  2048
#define C_  768
#define H_  12
#define D_  64
#define M_TOTAL (B_ * N_)        // 8192

// ---------------------------------------------------------------------------
// Scratch (__device__ globals; allocation-free rule)
// ---------------------------------------------------------------------------
__device__ __half g_xh[M_TOTAL * C_];            // x in fp16 [8192][768]
__device__ __half g_wqkvT[3 * C_ * C_];          // [2304][768] rows: q|k|v, K-major
__device__ __half g_wpT[C_ * C_];                // [768][768]
__device__ __half g_q[B_ * H_ * N_ * D_];        // [B,H,N,D] fp16 (pre-scaled)
__device__ __half g_k[B_ * H_ * N_ * D_];
__device__ __half g_v[B_ * H_ * N_ * D_];
__device__ __half g_attout[M_TOTAL * C_];        // [B,N,C] fp16

// ---------------------------------------------------------------------------
// helpers
// ---------------------------------------------------------------------------
__device__ __forceinline__ uint32_t sptr(const void* p) {
    return (uint32_t)__cvta_generic_to_shared(p);
}

__device__ __forceinline__ void cp16(uint32_t saddr, const void* g) {
    asm volatile("cp.async.cg.shared.global [%0], [%1], 16;"
                 :: "r"(saddr), "l"(__cvta_generic_to_global(g)));
}
#define CP_COMMIT() asm volatile("cp.async.commit_group;" ::: "memory")
#define CP_WAIT(n)  asm volatile("cp.async.wait_group %0;" :: "n"(n) : "memory")

__device__ __forceinline__ void ldm_x4(uint32_t& r0, uint32_t& r1, uint32_t& r2,
                                       uint32_t& r3, uint32_t addr) {
    asm volatile("ldmatrix.sync.aligned.m8n8.x4.shared.b16 {%0,%1,%2,%3}, [%4];"
                 : "=r"(r0), "=r"(r1), "=r"(r2), "=r"(r3) : "r"(addr));
}

__device__ __forceinline__ void ldm_x4_t(uint32_t& r0, uint32_t& r1, uint32_t& r2,
                                         uint32_t& r3, uint32_t addr) {
    asm volatile("ldmatrix.sync.aligned.m8n8.x4.trans.shared.b16 {%0,%1,%2,%3}, [%4];"
                 : "=r"(r0), "=r"(r1), "=r"(r2), "=r"(r3) : "r"(addr));
}

__device__ __forceinline__ void mma16816(float* c,
                                         uint32_t a0, uint32_t a1, uint32_t a2, uint32_t a3,
                                         uint32_t b0, uint32_t b1) {
    asm volatile(
        "mma.sync.aligned.m16n8k16.row.col.f32.f16.f16.f32 "
        "{%0,%1,%2,%3}, {%4,%5,%6,%7}, {%8,%9}, {%0,%1,%2,%3};"
        : "+f"(c[0]), "+f"(c[1]), "+f"(c[2]), "+f"(c[3])
        : "r"(a0), "r"(a1), "r"(a2), "r"(a3), "r"(b0), "r"(b1));
}

// ---------------------------------------------------------------------------
// fp32 -> fp16 convert (n multiple of 4)
// ---------------------------------------------------------------------------
__global__ void f2h_kernel(const float* __restrict__ src, __half* __restrict__ dst, int n)
{
    int i = (blockIdx.x * blockDim.x + threadIdx.x) * 4;
    if (i < n) {
        float4 v = *(const float4*)(src + i);
        *(__half2*)(dst + i)     = __floats2half2_rn(v.x, v.y);
        *(__half2*)(dst + i + 2) = __floats2half2_rn(v.z, v.w);
    }
}

// ---------------------------------------------------------------------------
// fp32 [K][N] -> fp16 [n][k] transpose
// ---------------------------------------------------------------------------
__global__ void transpose_h(const float* __restrict__ src, __half* __restrict__ dst,
                            int K, int N)
{
    __shared__ float t[32][33];
    const int k0 = blockIdx.y * 32;
    const int n0 = blockIdx.x * 32;
    const int tx = threadIdx.x;
    const int ty = threadIdx.y;
#pragma unroll
    for (int i = ty; i < 32; i += 8)
        t[i][tx] = src[(size_t)(k0 + i) * N + n0 + tx];
    __syncthreads();
#pragma unroll
    for (int i = ty; i < 32; i += 8)
        dst[(size_t)(n0 + i) * K + k0 + tx] = __float2half(t[tx][i]);
}

// ---------------------------------------------------------------------------
// hgemm: C[128,128] = A[128xK] * Bt[128xK]^T (K=768), 3-stage cp.async ring.
// 8 warps (4m x 2n), warp tile 32x64. smem row stride 40 halves.
// ---------------------------------------------------------------------------
#define AST 40
#define SSTRIDE (2 * 128 * AST)                 // halves per stage (A + B)
#define GEMM_SMEM (3 * SSTRIDE * 2)             // 61440 bytes

__device__ __forceinline__ void hgemm_issue(uint32_t sb,
                                            const __half* Ab, const __half* Bb,
                                            int c, int r0c, int q0c)
{
    const int k0 = c * 32;
    const int s = c % 3;
    const uint32_t abase = sb + (uint32_t)(s * SSTRIDE) * 2;
    const uint32_t bbase = abase + 128 * AST * 2;
#pragma unroll
    for (int i = 0; i < 2; i++) {
        uint32_t so = (uint32_t)(r0c * AST + (q0c + i) * 8) * 2;
        cp16(abase + so, Ab + (size_t)r0c * C_ + k0 + (q0c + i) * 8);
        cp16(bbase + so, Bb + (size_t)r0c * C_ + k0 + (q0c + i) * 8);
    }
}

template <int MODE>
__global__ __launch_bounds__(256) void hgemm(
    const __half* __restrict__ A, const __half* __restrict__ Bt,
    const float* __restrict__ bq, const float* __restrict__ bkv,
    float* __restrict__ outp)
{
    extern __shared__ __align__(16) __half sm[];
    const uint32_t sb = sptr(sm);

    const int tid = threadIdx.x;
    const int lane = tid & 31;
    const int wid = tid >> 5;
    const int wm = (wid >> 1) * 32;
    const int wn = (wid & 1) * 64;
    const int row0 = blockIdx.x * 128;
    const int n0   = blockIdx.y * 128;

    const __half* Ab = A  + (size_t)row0 * C_;
    const __half* Bb = Bt + (size_t)n0   * C_;

    const int r0c = (tid * 2) >> 2;
    const int q0c = (tid * 2) & 3;

    float acc[2][8][4];
#pragma unroll
    for (int i = 0; i < 2; i++)
#pragma unroll
        for (int j = 0; j < 8; j++)
#pragma unroll
            for (int q = 0; q < 4; q++) acc[i][j][q] = 0.f;

    hgemm_issue(sb, Ab, Bb, 0, r0c, q0c); CP_COMMIT();
    hgemm_issue(sb, Ab, Bb, 1, r0c, q0c); CP_COMMIT();

    for (int c = 0; c < 24; c++) {
        CP_WAIT(1);
        __syncthreads();
        if (c + 2 < 24) hgemm_issue(sb, Ab, Bb, c + 2, r0c, q0c);
        CP_COMMIT();

        const __half* Asb = sm + (c % 3) * SSTRIDE;
        const __half* Bsb = Asb + 128 * AST;
#pragma unroll
        for (int kk = 0; kk < 2; kk++) {
            uint32_t a[2][4];
#pragma unroll
            for (int i = 0; i < 2; i++) {
                int row = wm + i * 16 + (lane & 15);
                int col = kk * 16 + ((lane >> 4) << 3);
                ldm_x4(a[i][0], a[i][1], a[i][2], a[i][3],
                       sptr(&Asb[row * AST + col]));
            }
            uint32_t b[4][4];
#pragma unroll
            for (int p = 0; p < 4; p++) {
                int row = wn + p * 16 + ((lane >> 4) << 3) + (lane & 7);
                int col = kk * 16 + (((lane >> 3) & 1) << 3);
                ldm_x4(b[p][0], b[p][1], b[p][2], b[p][3],
                       sptr(&Bsb[row * AST + col]));
            }
#pragma unroll
            for (int i = 0; i < 2; i++)
#pragma unroll
                for (int j = 0; j < 8; j++) {
                    const uint32_t* bp = b[j >> 1];
                    mma16816(acc[i][j], a[i][0], a[i][1], a[i][2], a[i][3],
                             bp[(j & 1) * 2], bp[(j & 1) * 2 + 1]);
                }
        }
        __syncthreads();
    }

    // ------------------------- epilogue -------------------------
    const int gcol0 = n0 + wn;
    if (MODE == 0) {
        const int sel = gcol0 / C_;
        const float* bias = (sel == 0) ? (bq + gcol0) : (bkv + gcol0 - C_);
        __half* dstb = (sel == 0) ? g_q : (sel == 1) ? g_k : g_v;
        const int h = (gcol0 % C_) / D_;
        const float qs = (sel == 0) ? 0.125f : 1.0f;
#pragma unroll
        for (int i = 0; i < 2; i++) {
            int mlow = row0 + wm + i * 16 + (lane >> 2);
#pragma unroll
            for (int rh = 0; rh < 2; rh++) {
                int m = mlow + rh * 8;
                int bb = m >> 11;
                int nn = m & (N_ - 1);
                __half* drow = dstb + (size_t)((bb * H_ + h) * N_ + nn) * D_;
#pragma unroll
                for (int j = 0; j < 8; j++) {
                    int d = j * 8 + 2 * (lane & 3);
                    float2 bv = *(const float2*)(bias + d);
                    float v0 = (acc[i][j][rh * 2 + 0] + bv.x) * qs;
                    float v1 = (acc[i][j][rh * 2 + 1] + bv.y) * qs;
                    *(__half2*)(drow + d) = __floats2half2_rn(v0, v1);
                }
            }
        }
    } else {
#pragma unroll
        for (int i = 0; i < 2; i++) {
            int mlow = row0 + wm + i * 16 + (lane >> 2);
#pragma unroll
            for (int rh = 0; rh < 2; rh++) {
                int m = mlow + rh * 8;
                float* orow = outp + (size_t)m * C_ + gcol0;
#pragma unroll
                for (int j = 0; j < 8; j++) {
                    int d = j * 8 + 2 * (lane & 3);
                    float2 bv = *(const float2*)(bq + gcol0 + d);
                    float2 o;
                    o.x = acc[i][j][rh * 2 + 0] + bv.x;
                    o.y = acc[i][j][rh * 2 + 1] + bv.y;
                    *(float2*)(orow + d) = o;
                }
            }
        }
    }
}

// ---------------------------------------------------------------------------
// Flash attention on mma.sync with cp.async double-buffered K/V.
// CTA: 128 q rows of one (b,h); 8 warps x 16 rows; KV tiles of 64.
// smem (halves): Qs[128*72] | stage{0,1}: Ks[64*72], Vs[64*72]
// ---------------------------------------------------------------------------
#define QST 72
#define QS_H   (128 * QST)                      // 9216 halves
#define KVST_H (2 * 64 * QST)                   // halves per KV stage (K+V)
#define ATTN_SMEM ((QS_H + 2 * KVST_H) * 2)     // 55296 bytes

__device__ __forceinline__ void attn_issue_kv(uint32_t sb, const __half* kbase,
                                              const __half* vbase, int kt, int tid)
{
    const int s = kt & 1;
    const uint32_t kb0 = sb + (uint32_t)(QS_H + s * KVST_H) * 2;
    const uint32_t vb0 = kb0 + 64 * QST * 2;
    const __half* kg = kbase + (size_t)kt * 64 * D_;
    const __half* vg = vbase + (size_t)kt * 64 * D_;
#pragma unroll
    for (int i = 0; i < 2; i++) {
        int cch = tid + 256 * i;
        int r = cch >> 3, q = cch & 7;
        uint32_t so = (uint32_t)(r * QST + q * 8) * 2;
        cp16(kb0 + so, kg + (size_t)r * D_ + q * 8);
        cp16(vb0 + so, vg + (size_t)r * D_ + q * 8);
    }
}

__global__ __launch_bounds__(256) void attn_kernel()
{
    extern __shared__ __align__(16) __half sm[];
    const uint32_t sb = sptr(sm);

    const int qt = blockIdx.x;
    const int h  = blockIdx.y;
    const int b  = blockIdx.z;
    const int tid = threadIdx.x;
    const int lane = tid & 31;
    const int w = tid >> 5;

    const __half* qbase = g_q + (size_t)((b * H_ + h) * N_ + qt * 128) * D_;
    const __half* kbase = g_k + (size_t)(b * H_ + h) * N_ * D_;
    const __half* vbase = g_v + (size_t)(b * H_ + h) * N_ * D_;

    // group 0: Q tile + KV tile 0
#pragma unroll
    for (int i = 0; i < 4; i++) {
        int cch = tid + 256 * i;
        int r = cch >> 3, q = cch & 7;
        cp16(sb + (uint32_t)(r * QST + q * 8) * 2, qbase + (size_t)r * D_ + q * 8);
    }
    attn_issue_kv(sb, kbase, vbase, 0, tid);
    CP_COMMIT();

    uint32_t qa[4][4];
    float m0 = -CUDART_INF_F, m1 = -CUDART_INF_F;
    float l0 = 0.f, l1 = 0.f;
    float o[8][4];
#pragma unroll
    for (int j = 0; j < 8; j++)
#pragma unroll
        for (int q = 0; q < 4; q++) o[j][q] = 0.f;

    for (int kt = 0; kt < N_ / 64; kt++) {
        CP_WAIT(0);
        __syncthreads();
        if (kt == 0) {
#pragma unroll
            for (int kk = 0; kk < 4; kk++) {
                int row = w * 16 + (lane & 15);
                int col = kk * 16 + ((lane >> 4) << 3);
                ldm_x4(qa[kk][0], qa[kk][1], qa[kk][2], qa[kk][3],
                       sptr(&sm[row * QST + col]));
            }
        }
        if (kt + 1 < N_ / 64) attn_issue_kv(sb, kbase, vbase, kt + 1, tid);
        CP_COMMIT();

        const __half* Ks = sm + QS_H + (kt & 1) * KVST_H;
        const __half* Vs = Ks + 64 * QST;

        // S = Q K^T
        float s[8][4];
#pragma unroll
        for (int j = 0; j < 8; j++)
#pragma unroll
            for (int q = 0; q < 4; q++) s[j][q] = 0.f;

#pragma unroll
        for (int kk = 0; kk < 4; kk++) {
            uint32_t kb[4][4];
#pragma unroll
            for (int p = 0; p < 4; p++) {
                int row = p * 16 + ((lane >> 4) << 3) + (lane & 7);
                int col = kk * 16 + (((lane >> 3) & 1) << 3);
                ldm_x4(kb[p][0], kb[p][1], kb[p][2], kb[p][3],
                       sptr(&Ks[row * QST + col]));
            }
#pragma unroll
            for (int j = 0; j < 8; j++) {
                const uint32_t* bp = kb[j >> 1];
                mma16816(s[j], qa[kk][0], qa[kk][1], qa[kk][2], qa[kk][3],
                         bp[(j & 1) * 2], bp[(j & 1) * 2 + 1]);
            }
        }

        // online softmax
        float mx0 = -CUDART_INF_F, mx1 = -CUDART_INF_F;
#pragma unroll
        for (int j = 0; j < 8; j++) {
            mx0 = fmaxf(mx0, fmaxf(s[j][0], s[j][1]));
            mx1 = fmaxf(mx1, fmaxf(s[j][2], s[j][3]));
        }
        mx0 = fmaxf(mx0, __shfl_xor_sync(0xFFFFFFFFu, mx0, 1));
        mx0 = fmaxf(mx0, __shfl_xor_sync(0xFFFFFFFFu, mx0, 2));
        mx1 = fmaxf(mx1, __shfl_xor_sync(0xFFFFFFFFu, mx1, 1));
        mx1 = fmaxf(mx1, __shfl_xor_sync(0xFFFFFFFFu, mx1, 2));

        float nm0 = fmaxf(m0, mx0), nm1 = fmaxf(m1, mx1);
        float al0 = __expf(m0 - nm0), al1 = __expf(m1 - nm1);
        float sum0 = 0.f, sum1 = 0.f;
        __half2 pl[8], ph[8];
#pragma unroll
        for (int j = 0; j < 8; j++) {
            float e0 = __expf(s[j][0] - nm0);
            float e1 = __expf(s[j][1] - nm0);
            float e2 = __expf(s[j][2] - nm1);
            float e3 = __expf(s[j][3] - nm1);
            sum0 += e0 + e1;
            sum1 += e2 + e3;
            pl[j] = __floats2half2_rn(e0, e1);
            ph[j] = __floats2half2_rn(e2, e3);
        }
        sum0 += __shfl_xor_sync(0xFFFFFFFFu, sum0, 1);
        sum0 += __shfl_xor_sync(0xFFFFFFFFu, sum0, 2);
        sum1 += __shfl_xor_sync(0xFFFFFFFFu, sum1, 1);
        sum1 += __shfl_xor_sync(0xFFFFFFFFu, sum1, 2);

        l0 = l0 * al0 + sum0;
        l1 = l1 * al1 + sum1;
        m0 = nm0; m1 = nm1;
#pragma unroll
        for (int j = 0; j < 8; j++) {
            o[j][0] *= al0; o[j][1] *= al0;
            o[j][2] *= al1; o[j][3] *= al1;
        }

        // O += P V
#pragma unroll
        for (int t = 0; t < 4; t++) {
            uint32_t a0 = *(const uint32_t*)&pl[2 * t];
            uint32_t a1 = *(const uint32_t*)&ph[2 * t];
            uint32_t a2 = *(const uint32_t*)&pl[2 * t + 1];
            uint32_t a3 = *(const uint32_t*)&ph[2 * t + 1];
#pragma unroll
            for (int jd = 0; jd < 4; jd++) {
                uint32_t v0, v1, v2, v3;
                int row = t * 16 + (lane & 15);
                int col = jd * 16 + ((lane >> 4) << 3);
                ldm_x4_t(v0, v1, v2, v3, sptr(&Vs[row * QST + col]));
                mma16816(o[2 * jd],     a0, a1, a2, a3, v0, v1);
                mma16816(o[2 * jd + 1], a0, a1, a2, a3, v2, v3);
            }
        }
        __syncthreads();
    }

    // epilogue
    float inv0 = 1.f / l0, inv1 = 1.f / l1;
    int nlow = qt * 128 + w * 16 + (lane >> 2);
#pragma unroll
    for (int rh = 0; rh < 2; rh++) {
        int n = nlow + rh * 8;
        __half* drow = g_attout + (size_t)(b * N_ + n) * C_ + h * D_;
        float inv = rh ? inv1 : inv0;
#pragma unroll
        for (int j = 0; j < 8; j++) {
            int d = j * 8 + 2 * (lane & 3);
            *(__half2*)(drow + d) =
                __floats2half2_rn(o[j][rh * 2 + 0] * inv, o[j][rh * 2 + 1] * inv);
        }
    }
}

// ---------------------------------------------------------------------------
extern "C" void kernel_launch(void* const* d_in, const int* in_sizes, int n_in,
                              void* d_out, int out_size)
{
    const float* x   = (const float*)d_in[0];
    const float* wq  = (const float*)d_in[1];
    const float* bq  = (const float*)d_in[2];
    const float* wkv = (const float*)d_in[3];
    const float* bkv = (const float*)d_in[4];
    const float* wp  = (const float*)d_in[5];
    const float* bp  = (const float*)d_in[6];
    float* out = (float*)d_out;

    __half *xh, *wqkvT, *wpT, *attout;
    cudaGetSymbolAddress((void**)&xh,     g_xh);
    cudaGetSymbolAddress((void**)&wqkvT,  g_wqkvT);
    cudaGetSymbolAddress((void**)&wpT,    g_wpT);
    cudaGetSymbolAddress((void**)&attout, g_attout);

    cudaFuncSetAttribute(hgemm<0>, cudaFuncAttributeMaxDynamicSharedMemorySize, GEMM_SMEM);
    cudaFuncSetAttribute(hgemm<1>, cudaFuncAttributeMaxDynamicSharedMemorySize, GEMM_SMEM);
    cudaFuncSetAttribute(attn_kernel, cudaFuncAttributeMaxDynamicSharedMemorySize, ATTN_SMEM);

    f2h_kernel<<<(M_TOTAL * C_ / 4 + 255) / 256, 256>>>(x, xh, M_TOTAL * C_);
    transpose_h<<<dim3(C_ / 32, C_ / 32), dim3(32, 8)>>>(wq, wqkvT, C_, C_);
    transpose_h<<<dim3(2 * C_ / 32, C_ / 32), dim3(32, 8)>>>(wkv, wqkvT + (size_t)C_ * C_, C_, 2 * C_);
    transpose_h<<<dim3(C_ / 32, C_ / 32), dim3(32, 8)>>>(wp, wpT, C_, C_);

    hgemm<0><<<dim3(M_TOTAL / 128, (3 * C_) / 128), 256, GEMM_SMEM>>>(xh, wqkvT, bq, bkv, nullptr);
    attn_kernel<<<dim3(N_ / 128, H_, B_), 256, ATTN_SMEM>>>();
    hgemm<1><<<dim3(M_TOTAL / 128, C_ / 128), 256, GEMM_SMEM>>>(attout, wpT, bp, nullptr, out);
}

// round 5
// speedup vs baseline: 9.2277x; 1.0578x over previous
#include <cuda_runtime.h>
#include <cuda_fp16.h>
#include <math_constants.h>
#include <cstdint>

#define B_  4
#define N_  2048
#define C_  768
#define H_  12
#define D_  64
#define M_TOTAL (B_ * N_)        // 8192

// ---------------------------------------------------------------------------
// Scratch (__device__ globals; allocation-free rule)
// ---------------------------------------------------------------------------
__device__ __half g_xh[M_TOTAL * C_];            // x in fp16 [8192][768]
__device__ __half g_wqkvT[3 * C_ * C_];          // [2304][768] rows: q|k|v, K-major
__device__ __half g_wpT[C_ * C_];                // [768][768]
__device__ __half g_q[B_ * H_ * N_ * D_];        // [B,H,N,D] fp16 (pre-scaled)
__device__ __half g_k[B_ * H_ * N_ * D_];
__device__ __half g_v[B_ * H_ * N_ * D_];
__device__ __half g_attout[M_TOTAL * C_];        // [B,N,C] fp16

// ---------------------------------------------------------------------------
// helpers
// ---------------------------------------------------------------------------
__device__ __forceinline__ uint32_t sptr(const void* p) {
    return (uint32_t)__cvta_generic_to_shared(p);
}

__device__ __forceinline__ void cp16(uint32_t saddr, const void* g) {
    asm volatile("cp.async.cg.shared.global [%0], [%1], 16;"
                 :: "r"(saddr), "l"(__cvta_generic_to_global(g)));
}
#define CP_COMMIT() asm volatile("cp.async.commit_group;" ::: "memory")
#define CP_WAIT(n)  asm volatile("cp.async.wait_group %0;" :: "n"(n) : "memory")

__device__ __forceinline__ void ldm_x4(uint32_t& r0, uint32_t& r1, uint32_t& r2,
                                       uint32_t& r3, uint32_t addr) {
    asm volatile("ldmatrix.sync.aligned.m8n8.x4.shared.b16 {%0,%1,%2,%3}, [%4];"
                 : "=r"(r0), "=r"(r1), "=r"(r2), "=r"(r3) : "r"(addr));
}

__device__ __forceinline__ void ldm_x4_t(uint32_t& r0, uint32_t& r1, uint32_t& r2,
                                         uint32_t& r3, uint32_t addr) {
    asm volatile("ldmatrix.sync.aligned.m8n8.x4.trans.shared.b16 {%0,%1,%2,%3}, [%4];"
                 : "=r"(r0), "=r"(r1), "=r"(r2), "=r"(r3) : "r"(addr));
}

__device__ __forceinline__ void mma16816(float* c,
                                         uint32_t a0, uint32_t a1, uint32_t a2, uint32_t a3,
                                         uint32_t b0, uint32_t b1) {
    asm volatile(
        "mma.sync.aligned.m16n8k16.row.col.f32.f16.f16.f32 "
        "{%0,%1,%2,%3}, {%4,%5,%6,%7}, {%8,%9}, {%0,%1,%2,%3};"
        : "+f"(c[0]), "+f"(c[1]), "+f"(c[2]), "+f"(c[3])
        : "r"(a0), "r"(a1), "r"(a2), "r"(a3), "r"(b0), "r"(b1));
}

// ---------------------------------------------------------------------------
// fp32 -> fp16 convert
// ---------------------------------------------------------------------------
__global__ void f2h_kernel(const float* __restrict__ src, __half* __restrict__ dst, int n)
{
    int i = (blockIdx.x * blockDim.x + threadIdx.x) * 4;
    if (i < n) {
        float4 v = *(const float4*)(src + i);
        *(__half2*)(dst + i)     = __floats2half2_rn(v.x, v.y);
        *(__half2*)(dst + i + 2) = __floats2half2_rn(v.z, v.w);
    }
}

// ---------------------------------------------------------------------------
// all-weights fp32 [K][N] -> fp16 [n][k] transpose in one launch
// z=0: wq (N=C) -> g_wqkvT[0:C], z=1: wkv (N=2C) -> g_wqkvT[C:3C], z=2: wp -> g_wpT
// ---------------------------------------------------------------------------
__global__ void transpose_all(const float* __restrict__ wq,
                              const float* __restrict__ wkv,
                              const float* __restrict__ wp)
{
    __shared__ float t[32][33];
    const int z = blockIdx.z;
    const float* src;
    __half* dst;
    int N;
    if (z == 0)      { src = wq;  dst = g_wqkvT;                     N = C_; }
    else if (z == 1) { src = wkv; dst = g_wqkvT + (size_t)C_ * C_;   N = 2 * C_; }
    else             { src = wp;  dst = g_wpT;                       N = C_; }
    if (blockIdx.x * 32 >= N) return;

    const int k0 = blockIdx.y * 32;
    const int n0 = blockIdx.x * 32;
    const int tx = threadIdx.x;
    const int ty = threadIdx.y;
#pragma unroll
    for (int i = ty; i < 32; i += 8)
        t[i][tx] = src[(size_t)(k0 + i) * N + n0 + tx];
    __syncthreads();
#pragma unroll
    for (int i = ty; i < 32; i += 8)
        dst[(size_t)(n0 + i) * C_ + k0 + tx] = __float2half(t[tx][i]);
}

// ---------------------------------------------------------------------------
// hgemm: C[128,128] = A[128xK] * Bt[128xK]^T (K=768), 3-stage cp.async ring.
// 8 warps (4m x 2n), warp tile 32x64. 1 syncthreads per K-chunk.
// ---------------------------------------------------------------------------
#define AST 40
#define SSTRIDE (2 * 128 * AST)
#define GEMM_SMEM (3 * SSTRIDE * 2)             // 61440 bytes

__device__ __forceinline__ void hgemm_issue(uint32_t sb,
                                            const __half* Ab, const __half* Bb,
                                            int c, int r0c, int q0c)
{
    const int k0 = c * 32;
    const int s = c % 3;
    const uint32_t abase = sb + (uint32_t)(s * SSTRIDE) * 2;
    const uint32_t bbase = abase + 128 * AST * 2;
#pragma unroll
    for (int i = 0; i < 2; i++) {
        uint32_t so = (uint32_t)(r0c * AST + (q0c + i) * 8) * 2;
        cp16(abase + so, Ab + (size_t)r0c * C_ + k0 + (q0c + i) * 8);
        cp16(bbase + so, Bb + (size_t)r0c * C_ + k0 + (q0c + i) * 8);
    }
}

template <int MODE>
__global__ __launch_bounds__(256) void hgemm(
    const __half* __restrict__ A, const __half* __restrict__ Bt,
    const float* __restrict__ bq, const float* __restrict__ bkv,
    float* __restrict__ outp)
{
    extern __shared__ __align__(16) __half sm[];
    const uint32_t sb = sptr(sm);

    const int tid = threadIdx.x;
    const int lane = tid & 31;
    const int wid = tid >> 5;
    const int wm = (wid >> 1) * 32;
    const int wn = (wid & 1) * 64;
    const int row0 = blockIdx.x * 128;
    const int n0   = blockIdx.y * 128;

    const __half* Ab = A  + (size_t)row0 * C_;
    const __half* Bb = Bt + (size_t)n0   * C_;

    const int r0c = (tid * 2) >> 2;
    const int q0c = (tid * 2) & 3;

    float acc[2][8][4];
#pragma unroll
    for (int i = 0; i < 2; i++)
#pragma unroll
        for (int j = 0; j < 8; j++)
#pragma unroll
            for (int q = 0; q < 4; q++) acc[i][j][q] = 0.f;

    hgemm_issue(sb, Ab, Bb, 0, r0c, q0c); CP_COMMIT();
    hgemm_issue(sb, Ab, Bb, 1, r0c, q0c); CP_COMMIT();

    for (int c = 0; c < 24; c++) {
        CP_WAIT(1);
        __syncthreads();
        if (c + 2 < 24) hgemm_issue(sb, Ab, Bb, c + 2, r0c, q0c);
        CP_COMMIT();

        const __half* Asb = sm + (c % 3) * SSTRIDE;
        const __half* Bsb = Asb + 128 * AST;
#pragma unroll
        for (int kk = 0; kk < 2; kk++) {
            uint32_t a[2][4];
#pragma unroll
            for (int i = 0; i < 2; i++) {
                int row = wm + i * 16 + (lane & 15);
                int col = kk * 16 + ((lane >> 4) << 3);
                ldm_x4(a[i][0], a[i][1], a[i][2], a[i][3],
                       sptr(&Asb[row * AST + col]));
            }
            uint32_t b[4][4];
#pragma unroll
            for (int p = 0; p < 4; p++) {
                int row = wn + p * 16 + ((lane >> 4) << 3) + (lane & 7);
                int col = kk * 16 + (((lane >> 3) & 1) << 3);
                ldm_x4(b[p][0], b[p][1], b[p][2], b[p][3],
                       sptr(&Bsb[row * AST + col]));
            }
#pragma unroll
            for (int i = 0; i < 2; i++)
#pragma unroll
                for (int j = 0; j < 8; j++) {
                    const uint32_t* bp = b[j >> 1];
                    mma16816(acc[i][j], a[i][0], a[i][1], a[i][2], a[i][3],
                             bp[(j & 1) * 2], bp[(j & 1) * 2 + 1]);
                }
        }
        // no trailing sync: next iter's top sync orders compute(c) vs issue(c+3)
    }

    const int gcol0 = n0 + wn;
    if (MODE == 0) {
        const int sel = gcol0 / C_;
        const float* bias = (sel == 0) ? (bq + gcol0) : (bkv + gcol0 - C_);
        __half* dstb = (sel == 0) ? g_q : (sel == 1) ? g_k : g_v;
        const int h = (gcol0 % C_) / D_;
        const float qs = (sel == 0) ? 0.125f : 1.0f;
#pragma unroll
        for (int i = 0; i < 2; i++) {
            int mlow = row0 + wm + i * 16 + (lane >> 2);
#pragma unroll
            for (int rh = 0; rh < 2; rh++) {
                int m = mlow + rh * 8;
                int bb = m >> 11;
                int nn = m & (N_ - 1);
                __half* drow = dstb + (size_t)((bb * H_ + h) * N_ + nn) * D_;
#pragma unroll
                for (int j = 0; j < 8; j++) {
                    int d = j * 8 + 2 * (lane & 3);
                    float2 bv = *(const float2*)(bias + d);
                    float v0 = (acc[i][j][rh * 2 + 0] + bv.x) * qs;
                    float v1 = (acc[i][j][rh * 2 + 1] + bv.y) * qs;
                    *(__half2*)(drow + d) = __floats2half2_rn(v0, v1);
                }
            }
        }
    } else {
#pragma unroll
        for (int i = 0; i < 2; i++) {
            int mlow = row0 + wm + i * 16 + (lane >> 2);
#pragma unroll
            for (int rh = 0; rh < 2; rh++) {
                int m = mlow + rh * 8;
                float* orow = outp + (size_t)m * C_ + gcol0;
#pragma unroll
                for (int j = 0; j < 8; j++) {
                    int d = j * 8 + 2 * (lane & 3);
                    float2 bv = *(const float2*)(bq + gcol0 + d);
                    float2 o;
                    o.x = acc[i][j][rh * 2 + 0] + bv.x;
                    o.y = acc[i][j][rh * 2 + 1] + bv.y;
                    *(float2*)(orow + d) = o;
                }
            }
        }
    }
}

// ---------------------------------------------------------------------------
// Flash attention v3: CTA = 256 q rows of one (b,h); 8 warps; each warp owns
// two 16-row m-tiles (rows w*16 + {0,128}). KV tiles of 64, double-buffered
// cp.async, K/V fragments shared across both m-tiles (ldm:mma = 1:4).
// smem (halves): Qs[256*72] | stage{0,1}: Ks[64*72], Vs[64*72]
// ---------------------------------------------------------------------------
#define QST 72
#define QROWS 256
#define QS_H   (QROWS * QST)                    // 18432 halves
#define KVST_H (2 * 64 * QST)                   // 9216 halves per stage
#define ATTN_SMEM ((QS_H + 2 * KVST_H) * 2)     // 73728 bytes

__device__ __forceinline__ void attn_issue_kv(uint32_t sb, const __half* kbase,
                                              const __half* vbase, int kt, int tid)
{
    const int s = kt & 1;
    const uint32_t kb0 = sb + (uint32_t)(QS_H + s * KVST_H) * 2;
    const uint32_t vb0 = kb0 + 64 * QST * 2;
    const __half* kg = kbase + (size_t)kt * 64 * D_;
    const __half* vg = vbase + (size_t)kt * 64 * D_;
#pragma unroll
    for (int i = 0; i < 2; i++) {
        int cch = tid + 256 * i;
        int r = cch >> 3, q = cch & 7;
        uint32_t so = (uint32_t)(r * QST + q * 8) * 2;
        cp16(kb0 + so, kg + (size_t)r * D_ + q * 8);
        cp16(vb0 + so, vg + (size_t)r * D_ + q * 8);
    }
}

__global__ __launch_bounds__(256) void attn_kernel()
{
    extern __shared__ __align__(16) __half sm[];
    const uint32_t sb = sptr(sm);

    const int qt = blockIdx.x;       // 8 tiles of 256 q rows
    const int h  = blockIdx.y;
    const int b  = blockIdx.z;
    const int tid = threadIdx.x;
    const int lane = tid & 31;
    const int w = tid >> 5;

    const __half* qbase = g_q + (size_t)((b * H_ + h) * N_ + qt * QROWS) * D_;
    const __half* kbase = g_k + (size_t)(b * H_ + h) * N_ * D_;
    const __half* vbase = g_v + (size_t)(b * H_ + h) * N_ * D_;

    // group 0: Q tile (256 rows x 8 chunks = 2048 chunks, 8/thread) + KV tile 0
#pragma unroll
    for (int i = 0; i < 8; i++) {
        int cch = tid + 256 * i;
        int r = cch >> 3, q = cch & 7;
        cp16(sb + (uint32_t)(r * QST + q * 8) * 2, qbase + (size_t)r * D_ + q * 8);
    }
    attn_issue_kv(sb, kbase, vbase, 0, tid);
    CP_COMMIT();

    uint32_t qa[2][4][4];
    float mr[2][2], lr[2][2];
    float o[2][8][4];
#pragma unroll
    for (int i = 0; i < 2; i++) {
        mr[i][0] = -CUDART_INF_F; mr[i][1] = -CUDART_INF_F;
        lr[i][0] = 0.f; lr[i][1] = 0.f;
#pragma unroll
        for (int j = 0; j < 8; j++)
#pragma unroll
            for (int q = 0; q < 4; q++) o[i][j][q] = 0.f;
    }

    for (int kt = 0; kt < N_ / 64; kt++) {
        CP_WAIT(0);
        __syncthreads();
        if (kt == 0) {
#pragma unroll
            for (int i = 0; i < 2; i++)
#pragma unroll
                for (int kk = 0; kk < 4; kk++) {
                    int row = i * 128 + w * 16 + (lane & 15);
                    int col = kk * 16 + ((lane >> 4) << 3);
                    ldm_x4(qa[i][kk][0], qa[i][kk][1], qa[i][kk][2], qa[i][kk][3],
                           sptr(&sm[row * QST + col]));
                }
        }
        if (kt + 1 < N_ / 64) attn_issue_kv(sb, kbase, vbase, kt + 1, tid);
        CP_COMMIT();

        const __half* Ks = sm + QS_H + (kt & 1) * KVST_H;
        const __half* Vs = Ks + 64 * QST;

        // S = Q K^T for both m-tiles (K frags shared)
        float s[2][8][4];
#pragma unroll
        for (int i = 0; i < 2; i++)
#pragma unroll
            for (int j = 0; j < 8; j++)
#pragma unroll
                for (int q = 0; q < 4; q++) s[i][j][q] = 0.f;

#pragma unroll
        for (int kk = 0; kk < 4; kk++) {
            uint32_t kb[4][4];
#pragma unroll
            for (int p = 0; p < 4; p++) {
                int row = p * 16 + ((lane >> 4) << 3) + (lane & 7);
                int col = kk * 16 + (((lane >> 3) & 1) << 3);
                ldm_x4(kb[p][0], kb[p][1], kb[p][2], kb[p][3],
                       sptr(&Ks[row * QST + col]));
            }
#pragma unroll
            for (int i = 0; i < 2; i++)
#pragma unroll
                for (int j = 0; j < 8; j++) {
                    const uint32_t* bp = kb[j >> 1];
                    mma16816(s[i][j], qa[i][kk][0], qa[i][kk][1], qa[i][kk][2], qa[i][kk][3],
                             bp[(j & 1) * 2], bp[(j & 1) * 2 + 1]);
                }
        }

        // online softmax per m-tile
        __half2 pl[2][8], ph[2][8];
#pragma unroll
        for (int i = 0; i < 2; i++) {
            float mx0 = -CUDART_INF_F, mx1 = -CUDART_INF_F;
#pragma unroll
            for (int j = 0; j < 8; j++) {
                mx0 = fmaxf(mx0, fmaxf(s[i][j][0], s[i][j][1]));
                mx1 = fmaxf(mx1, fmaxf(s[i][j][2], s[i][j][3]));
            }
            mx0 = fmaxf(mx0, __shfl_xor_sync(0xFFFFFFFFu, mx0, 1));
            mx0 = fmaxf(mx0, __shfl_xor_sync(0xFFFFFFFFu, mx0, 2));
            mx1 = fmaxf(mx1, __shfl_xor_sync(0xFFFFFFFFu, mx1, 1));
            mx1 = fmaxf(mx1, __shfl_xor_sync(0xFFFFFFFFu, mx1, 2));

            float nm0 = fmaxf(mr[i][0], mx0), nm1 = fmaxf(mr[i][1], mx1);
            float al0 = __expf(mr[i][0] - nm0), al1 = __expf(mr[i][1] - nm1);
            float sum0 = 0.f, sum1 = 0.f;
#pragma unroll
            for (int j = 0; j < 8; j++) {
                float e0 = __expf(s[i][j][0] - nm0);
                float e1 = __expf(s[i][j][1] - nm0);
                float e2 = __expf(s[i][j][2] - nm1);
                float e3 = __expf(s[i][j][3] - nm1);
                sum0 += e0 + e1;
                sum1 += e2 + e3;
                pl[i][j] = __floats2half2_rn(e0, e1);
                ph[i][j] = __floats2half2_rn(e2, e3);
            }
            sum0 += __shfl_xor_sync(0xFFFFFFFFu, sum0, 1);
            sum0 += __shfl_xor_sync(0xFFFFFFFFu, sum0, 2);
            sum1 += __shfl_xor_sync(0xFFFFFFFFu, sum1, 1);
            sum1 += __shfl_xor_sync(0xFFFFFFFFu, sum1, 2);

            lr[i][0] = lr[i][0] * al0 + sum0;
            lr[i][1] = lr[i][1] * al1 + sum1;
            mr[i][0] = nm0; mr[i][1] = nm1;
#pragma unroll
            for (int j = 0; j < 8; j++) {
                o[i][j][0] *= al0; o[i][j][1] *= al0;
                o[i][j][2] *= al1; o[i][j][3] *= al1;
            }
        }

        // O += P V (V frags shared across m-tiles)
#pragma unroll
        for (int t = 0; t < 4; t++) {
#pragma unroll
            for (int jd = 0; jd < 4; jd++) {
                uint32_t v0, v1, v2, v3;
                int row = t * 16 + (lane & 15);
                int col = jd * 16 + ((lane >> 4) << 3);
                ldm_x4_t(v0, v1, v2, v3, sptr(&Vs[row * QST + col]));
#pragma unroll
                for (int i = 0; i < 2; i++) {
                    uint32_t a0 = *(const uint32_t*)&pl[i][2 * t];
                    uint32_t a1 = *(const uint32_t*)&ph[i][2 * t];
                    uint32_t a2 = *(const uint32_t*)&pl[i][2 * t + 1];
                    uint32_t a3 = *(const uint32_t*)&ph[i][2 * t + 1];
                    mma16816(o[i][2 * jd],     a0, a1, a2, a3, v0, v1);
                    mma16816(o[i][2 * jd + 1], a0, a1, a2, a3, v2, v3);
                }
            }
        }
        // no trailing sync: next iter's top sync orders this compute vs overwrite
    }

    // epilogue
#pragma unroll
    for (int i = 0; i < 2; i++) {
        float inv0 = 1.f / lr[i][0], inv1 = 1.f / lr[i][1];
        int nlow = qt * QROWS + i * 128 + w * 16 + (lane >> 2);
#pragma unroll
        for (int rh = 0; rh < 2; rh++) {
            int n = nlow + rh * 8;
            __half* drow = g_attout + (size_t)(b * N_ + n) * C_ + h * D_;
            float inv = rh ? inv1 : inv0;
#pragma unroll
            for (int j = 0; j < 8; j++) {
                int d = j * 8 + 2 * (lane & 3);
                *(__half2*)(drow + d) =
                    __floats2half2_rn(o[i][j][rh * 2 + 0] * inv, o[i][j][rh * 2 + 1] * inv);
            }
        }
    }
}

// ---------------------------------------------------------------------------
extern "C" void kernel_launch(void* const* d_in, const int* in_sizes, int n_in,
                              void* d_out, int out_size)
{
    const float* x   = (const float*)d_in[0];
    const float* wq  = (const float*)d_in[1];
    const float* bq  = (const float*)d_in[2];
    const float* wkv = (const float*)d_in[3];
    const float* bkv = (const float*)d_in[4];
    const float* wp  = (const float*)d_in[5];
    const float* bp  = (const float*)d_in[6];
    float* out = (float*)d_out;

    __half *xh, *wqkvT, *wpT, *attout;
    cudaGetSymbolAddress((void**)&xh,     g_xh);
    cudaGetSymbolAddress((void**)&wqkvT,  g_wqkvT);
    cudaGetSymbolAddress((void**)&wpT,    g_wpT);
    cudaGetSymbolAddress((void**)&attout, g_attout);

    cudaFuncSetAttribute(hgemm<0>, cudaFuncAttributeMaxDynamicSharedMemorySize, GEMM_SMEM);
    cudaFuncSetAttribute(hgemm<1>, cudaFuncAttributeMaxDynamicSharedMemorySize, GEMM_SMEM);
    cudaFuncSetAttribute(attn_kernel, cudaFuncAttributeMaxDynamicSharedMemorySize, ATTN_SMEM);

    f2h_kernel<<<(M_TOTAL * C_ / 4 + 255) / 256, 256>>>(x, xh, M_TOTAL * C_);
    transpose_all<<<dim3(2 * C_ / 32, C_ / 32, 3), dim3(32, 8)>>>(wq, wkv, wp);

    hgemm<0><<<dim3(M_TOTAL / 128, (3 * C_) / 128), 256, GEMM_SMEM>>>(xh, wqkvT, bq, bkv, nullptr);
    attn_kernel<<<dim3(N_ / QROWS, H_, B_), 256, ATTN_SMEM>>>();
    hgemm<1><<<dim3(M_TOTAL / 128, C_ / 128), 256, GEMM_SMEM>>>(attout, wpT, bp, nullptr, out);
}

// round 7
// speedup vs baseline: 9.6511x; 1.0459x over previous
#include <cuda_runtime.h>
#include <cuda_fp16.h>
#include <math_constants.h>
#include <cstdint>

#define B_  4
#define N_  2048
#define C_  768
#define H_  12
#define D_  64
#define M_TOTAL (B_ * N_)        // 8192

// ---------------------------------------------------------------------------
// Scratch (__device__ globals; allocation-free rule)
// ---------------------------------------------------------------------------
__device__ __half g_xh[M_TOTAL * C_];            // x in fp16 [8192][768]
__device__ __half g_wqkvT[3 * C_ * C_];          // [2304][768] rows: q|k|v, K-major
__device__ __half g_wpT[C_ * C_];                // [768][768]
__device__ __half g_q[B_ * H_ * N_ * D_];        // [B,H,N,D] fp16 (pre-scaled by 0.125*log2e)
__device__ __half g_k[B_ * H_ * N_ * D_];
__device__ __half g_v[B_ * H_ * N_ * D_];
__device__ __half g_attout[M_TOTAL * C_];        // [B,N,C] fp16

// ---------------------------------------------------------------------------
// helpers
// ---------------------------------------------------------------------------
__device__ __forceinline__ uint32_t sptr(const void* p) {
    return (uint32_t)__cvta_generic_to_shared(p);
}

__device__ __forceinline__ void cp16(uint32_t saddr, const void* g) {
    asm volatile("cp.async.cg.shared.global [%0], [%1], 16;"
                 :: "r"(saddr), "l"(__cvta_generic_to_global(g)));
}
#define CP_COMMIT() asm volatile("cp.async.commit_group;" ::: "memory")
#define CP_WAIT(n)  asm volatile("cp.async.wait_group %0;" :: "n"(n) : "memory")

__device__ __forceinline__ void ldm_x4(uint32_t& r0, uint32_t& r1, uint32_t& r2,
                                       uint32_t& r3, uint32_t addr) {
    asm volatile("ldmatrix.sync.aligned.m8n8.x4.shared.b16 {%0,%1,%2,%3}, [%4];"
                 : "=r"(r0), "=r"(r1), "=r"(r2), "=r"(r3) : "r"(addr));
}

__device__ __forceinline__ void ldm_x4_t(uint32_t& r0, uint32_t& r1, uint32_t& r2,
                                         uint32_t& r3, uint32_t addr) {
    asm volatile("ldmatrix.sync.aligned.m8n8.x4.trans.shared.b16 {%0,%1,%2,%3}, [%4];"
                 : "=r"(r0), "=r"(r1), "=r"(r2), "=r"(r3) : "r"(addr));
}

__device__ __forceinline__ void mma16816(float* c,
                                         uint32_t a0, uint32_t a1, uint32_t a2, uint32_t a3,
                                         uint32_t b0, uint32_t b1) {
    asm volatile(
        "mma.sync.aligned.m16n8k16.row.col.f32.f16.f16.f32 "
        "{%0,%1,%2,%3}, {%4,%5,%6,%7}, {%8,%9}, {%0,%1,%2,%3};"
        : "+f"(c[0]), "+f"(c[1]), "+f"(c[2]), "+f"(c[3])
        : "r"(a0), "r"(a1), "r"(a2), "r"(a3), "r"(b0), "r"(b1));
}

// half2 2^x (approx) — one MUFU per pair, fp16 result feeds mma directly
__device__ __forceinline__ __half2 hexp2_(__half2 x) {
    uint32_t r, xi = *(const uint32_t*)&x;
    asm("ex2.approx.f16x2 %0, %1;" : "=r"(r) : "r"(xi));
    return *(__half2*)&r;
}

// ---------------------------------------------------------------------------
// fp32 -> fp16 convert
// ---------------------------------------------------------------------------
__global__ void f2h_kernel(const float* __restrict__ src, __half* __restrict__ dst, int n)
{
    int i = (blockIdx.x * blockDim.x + threadIdx.x) * 4;
    if (i < n) {
        float4 v = *(const float4*)(src + i);
        *(__half2*)(dst + i)     = __floats2half2_rn(v.x, v.y);
        *(__half2*)(dst + i + 2) = __floats2half2_rn(v.z, v.w);
    }
}

// ---------------------------------------------------------------------------
// all-weights fp32 [K][N] -> fp16 [n][k] transpose in one launch
// ---------------------------------------------------------------------------
__global__ void transpose_all(const float* __restrict__ wq,
                              const float* __restrict__ wkv,
                              const float* __restrict__ wp)
{
    __shared__ float t[32][33];
    const int z = blockIdx.z;
    const float* src;
    __half* dst;
    int N;
    if (z == 0)      { src = wq;  dst = g_wqkvT;                     N = C_; }
    else if (z == 1) { src = wkv; dst = g_wqkvT + (size_t)C_ * C_;   N = 2 * C_; }
    else             { src = wp;  dst = g_wpT;                       N = C_; }
    if (blockIdx.x * 32 >= N) return;

    const int k0 = blockIdx.y * 32;
    const int n0 = blockIdx.x * 32;
    const int tx = threadIdx.x;
    const int ty = threadIdx.y;
#pragma unroll
    for (int i = ty; i < 32; i += 8)
        t[i][tx] = src[(size_t)(k0 + i) * N + n0 + tx];
    __syncthreads();
#pragma unroll
    for (int i = ty; i < 32; i += 8)
        dst[(size_t)(n0 + i) * C_ + k0 + tx] = __float2half(t[tx][i]);
}

// ---------------------------------------------------------------------------
// hgemm: C[128,128] = A[128xK] * Bt[128xK]^T (K=768), 3-stage cp.async ring.
// ---------------------------------------------------------------------------
#define AST 40
#define SSTRIDE (2 * 128 * AST)
#define GEMM_SMEM (3 * SSTRIDE * 2)             // 61440 bytes

__device__ __forceinline__ void hgemm_issue(uint32_t sb,
                                            const __half* Ab, const __half* Bb,
                                            int c, int r0c, int q0c)
{
    const int k0 = c * 32;
    const int s = c % 3;
    const uint32_t abase = sb + (uint32_t)(s * SSTRIDE) * 2;
    const uint32_t bbase = abase + 128 * AST * 2;
#pragma unroll
    for (int i = 0; i < 2; i++) {
        uint32_t so = (uint32_t)(r0c * AST + (q0c + i) * 8) * 2;
        cp16(abase + so, Ab + (size_t)r0c * C_ + k0 + (q0c + i) * 8);
        cp16(bbase + so, Bb + (size_t)r0c * C_ + k0 + (q0c + i) * 8);
    }
}

template <int MODE>
__global__ __launch_bounds__(256, 2) void hgemm(
    const __half* __restrict__ A, const __half* __restrict__ Bt,
    const float* __restrict__ bq, const float* __restrict__ bkv,
    float* __restrict__ outp)
{
    extern __shared__ __align__(16) __half sm[];
    const uint32_t sb = sptr(sm);

    const int tid = threadIdx.x;
    const int lane = tid & 31;
    const int wid = tid >> 5;
    const int wm = (wid >> 1) * 32;
    const int wn = (wid & 1) * 64;
    const int row0 = blockIdx.x * 128;
    const int n0   = blockIdx.y * 128;

    const __half* Ab = A  + (size_t)row0 * C_;
    const __half* Bb = Bt + (size_t)n0   * C_;

    const int r0c = (tid * 2) >> 2;
    const int q0c = (tid * 2) & 3;

    float acc[2][8][4];
#pragma unroll
    for (int i = 0; i < 2; i++)
#pragma unroll
        for (int j = 0; j < 8; j++)
#pragma unroll
            for (int q = 0; q < 4; q++) acc[i][j][q] = 0.f;

    hgemm_issue(sb, Ab, Bb, 0, r0c, q0c); CP_COMMIT();
    hgemm_issue(sb, Ab, Bb, 1, r0c, q0c); CP_COMMIT();

    for (int c = 0; c < 24; c++) {
        CP_WAIT(1);
        __syncthreads();
        if (c + 2 < 24) hgemm_issue(sb, Ab, Bb, c + 2, r0c, q0c);
        CP_COMMIT();

        const __half* Asb = sm + (c % 3) * SSTRIDE;
        const __half* Bsb = Asb + 128 * AST;
#pragma unroll
        for (int kk = 0; kk < 2; kk++) {
            uint32_t a[2][4];
#pragma unroll
            for (int i = 0; i < 2; i++) {
                int row = wm + i * 16 + (lane & 15);
                int col = kk * 16 + ((lane >> 4) << 3);
                ldm_x4(a[i][0], a[i][1], a[i][2], a[i][3],
                       sptr(&Asb[row * AST + col]));
            }
            uint32_t b[4][4];
#pragma unroll
            for (int p = 0; p < 4; p++) {
                int row = wn + p * 16 + ((lane >> 4) << 3) + (lane & 7);
                int col = kk * 16 + (((lane >> 3) & 1) << 3);
                ldm_x4(b[p][0], b[p][1], b[p][2], b[p][3],
                       sptr(&Bsb[row * AST + col]));
            }
#pragma unroll
            for (int i = 0; i < 2; i++)
#pragma unroll
                for (int j = 0; j < 8; j++) {
                    const uint32_t* bp = b[j >> 1];
                    mma16816(acc[i][j], a[i][0], a[i][1], a[i][2], a[i][3],
                             bp[(j & 1) * 2], bp[(j & 1) * 2 + 1]);
                }
        }
    }

    const int gcol0 = n0 + wn;
    if (MODE == 0) {
        const int sel = gcol0 / C_;
        const float* bias = (sel == 0) ? (bq + gcol0) : (bkv + gcol0 - C_);
        __half* dstb = (sel == 0) ? g_q : (sel == 1) ? g_k : g_v;
        const int h = (gcol0 % C_) / D_;
        // q pre-scale: D^-0.5 * log2(e) so attention can use exp2 directly
        const float qs = (sel == 0) ? 0.18033688011112042f : 1.0f;
#pragma unroll
        for (int i = 0; i < 2; i++) {
            int mlow = row0 + wm + i * 16 + (lane >> 2);
#pragma unroll
            for (int rh = 0; rh < 2; rh++) {
                int m = mlow + rh * 8;
                int bb = m >> 11;
                int nn = m & (N_ - 1);
                __half* drow = dstb + (size_t)((bb * H_ + h) * N_ + nn) * D_;
#pragma unroll
                for (int j = 0; j < 8; j++) {
                    int d = j * 8 + 2 * (lane & 3);
                    float2 bv = *(const float2*)(bias + d);
                    float v0 = (acc[i][j][rh * 2 + 0] + bv.x) * qs;
                    float v1 = (acc[i][j][rh * 2 + 1] + bv.y) * qs;
                    *(__half2*)(drow + d) = __floats2half2_rn(v0, v1);
                }
            }
        }
    } else {
#pragma unroll
        for (int i = 0; i < 2; i++) {
            int mlow = row0 + wm + i * 16 + (lane >> 2);
#pragma unroll
            for (int rh = 0; rh < 2; rh++) {
                int m = mlow + rh * 8;
                float* orow = outp + (size_t)m * C_ + gcol0;
#pragma unroll
                for (int j = 0; j < 8; j++) {
                    int d = j * 8 + 2 * (lane & 3);
                    float2 bv = *(const float2*)(bq + gcol0 + d);
                    float2 o;
                    o.x = acc[i][j][rh * 2 + 0] + bv.x;
                    o.y = acc[i][j][rh * 2 + 1] + bv.y;
                    *(float2*)(orow + d) = o;
                }
            }
        }
    }
}

// ---------------------------------------------------------------------------
// Flash attention v4: 256 q rows/CTA, 8 warps, 2 m-tiles/warp, KV tiles of 64.
// Softmax in base-2 (Q pre-scaled by log2e): ex2.approx.f16x2, fp16 P,
// row-sums from the same quantized fp16 P (numerator/denominator cancel).
// ---------------------------------------------------------------------------
#define QST 72
#define QROWS 256
#define QS_H   (QROWS * QST)
#define KVST_H (2 * 64 * QST)
#define ATTN_SMEM ((QS_H + 2 * KVST_H) * 2)     // 73728 bytes

__device__ __forceinline__ void attn_issue_kv(uint32_t sb, const __half* kbase,
                                              const __half* vbase, int kt, int tid)
{
    const int s = kt & 1;
    const uint32_t kb0 = sb + (uint32_t)(QS_H + s * KVST_H) * 2;
    const uint32_t vb0 = kb0 + 64 * QST * 2;
    const __half* kg = kbase + (size_t)kt * 64 * D_;
    const __half* vg = vbase + (size_t)kt * 64 * D_;
#pragma unroll
    for (int i = 0; i < 2; i++) {
        int cch = tid + 256 * i;
        int r = cch >> 3, q = cch & 7;
        uint32_t so = (uint32_t)(r * QST + q * 8) * 2;
        cp16(kb0 + so, kg + (size_t)r * D_ + q * 8);
        cp16(vb0 + so, vg + (size_t)r * D_ + q * 8);
    }
}

__global__ __launch_bounds__(256) void attn_kernel()
{
    extern __shared__ __align__(16) __half sm[];
    const uint32_t sb = sptr(sm);

    const int qt = blockIdx.x;
    const int h  = blockIdx.y;
    const int b  = blockIdx.z;
    const int tid = threadIdx.x;
    const int lane = tid & 31;
    const int w = tid >> 5;

    const __half* qbase = g_q + (size_t)((b * H_ + h) * N_ + qt * QROWS) * D_;
    const __half* kbase = g_k + (size_t)(b * H_ + h) * N_ * D_;
    const __half* vbase = g_v + (size_t)(b * H_ + h) * N_ * D_;

#pragma unroll
    for (int i = 0; i < 8; i++) {
        int cch = tid + 256 * i;
        int r = cch >> 3, q = cch & 7;
        cp16(sb + (uint32_t)(r * QST + q * 8) * 2, qbase + (size_t)r * D_ + q * 8);
    }
    attn_issue_kv(sb, kbase, vbase, 0, tid);
    CP_COMMIT();

    uint32_t qa[2][4][4];
    float mr[2][2], lr[2][2];
    float o[2][8][4];
#pragma unroll
    for (int i = 0; i < 2; i++) {
        mr[i][0] = -CUDART_INF_F; mr[i][1] = -CUDART_INF_F;
        lr[i][0] = 0.f; lr[i][1] = 0.f;
#pragma unroll
        for (int j = 0; j < 8; j++)
#pragma unroll
            for (int q = 0; q < 4; q++) o[i][j][q] = 0.f;
    }

    for (int kt = 0; kt < N_ / 64; kt++) {
        CP_WAIT(0);
        __syncthreads();
        if (kt == 0) {
#pragma unroll
            for (int i = 0; i < 2; i++)
#pragma unroll
                for (int kk = 0; kk < 4; kk++) {
                    int row = i * 128 + w * 16 + (lane & 15);
                    int col = kk * 16 + ((lane >> 4) << 3);
                    ldm_x4(qa[i][kk][0], qa[i][kk][1], qa[i][kk][2], qa[i][kk][3],
                           sptr(&sm[row * QST + col]));
                }
        }
        if (kt + 1 < N_ / 64) attn_issue_kv(sb, kbase, vbase, kt + 1, tid);
        CP_COMMIT();

        const __half* Ks = sm + QS_H + (kt & 1) * KVST_H;
        const __half* Vs = Ks + 64 * QST;

        // S = Q K^T (base-2 logits; scale folded into Q)
        float s[2][8][4];
#pragma unroll
        for (int i = 0; i < 2; i++)
#pragma unroll
            for (int j = 0; j < 8; j++)
#pragma unroll
                for (int q = 0; q < 4; q++) s[i][j][q] = 0.f;

#pragma unroll
        for (int kk = 0; kk < 4; kk++) {
            uint32_t kb[4][4];
#pragma unroll
            for (int p = 0; p < 4; p++) {
                int row = p * 16 + ((lane >> 4) << 3) + (lane & 7);
                int col = kk * 16 + (((lane >> 3) & 1) << 3);
                ldm_x4(kb[p][0], kb[p][1], kb[p][2], kb[p][3],
                       sptr(&Ks[row * QST + col]));
            }
#pragma unroll
            for (int i = 0; i < 2; i++)
#pragma unroll
                for (int j = 0; j < 8; j++) {
                    const uint32_t* bp = kb[j >> 1];
                    mma16816(s[i][j], qa[i][kk][0], qa[i][kk][1], qa[i][kk][2], qa[i][kk][3],
                             bp[(j & 1) * 2], bp[(j & 1) * 2 + 1]);
                }
        }

        // online softmax per m-tile (base 2, fp16 exponentials)
        __half2 pl[2][8], ph[2][8];
#pragma unroll
        for (int i = 0; i < 2; i++) {
            float mx0 = -CUDART_INF_F, mx1 = -CUDART_INF_F;
#pragma unroll
            for (int j = 0; j < 8; j++) {
                mx0 = fmaxf(mx0, fmaxf(s[i][j][0], s[i][j][1]));
                mx1 = fmaxf(mx1, fmaxf(s[i][j][2], s[i][j][3]));
            }
            mx0 = fmaxf(mx0, __shfl_xor_sync(0xFFFFFFFFu, mx0, 1));
            mx0 = fmaxf(mx0, __shfl_xor_sync(0xFFFFFFFFu, mx0, 2));
            mx1 = fmaxf(mx1, __shfl_xor_sync(0xFFFFFFFFu, mx1, 1));
            mx1 = fmaxf(mx1, __shfl_xor_sync(0xFFFFFFFFu, mx1, 2));

            float nm0 = fmaxf(mr[i][0], mx0), nm1 = fmaxf(mr[i][1], mx1);
            float al0 = exp2f(mr[i][0] - nm0), al1 = exp2f(mr[i][1] - nm1);
#pragma unroll
            for (int j = 0; j < 8; j++) {
                pl[i][j] = hexp2_(__floats2half2_rn(s[i][j][0] - nm0, s[i][j][1] - nm0));
                ph[i][j] = hexp2_(__floats2half2_rn(s[i][j][2] - nm1, s[i][j][3] - nm1));
            }
            // row sums of the quantized fp16 P (pairwise hadd2, fp32 accumulate)
            float sum0 = 0.f, sum1 = 0.f;
#pragma unroll
            for (int jj = 0; jj < 4; jj++) {
                float2 f0 = __half22float2(__hadd2(pl[i][2 * jj], pl[i][2 * jj + 1]));
                float2 f1 = __half22float2(__hadd2(ph[i][2 * jj], ph[i][2 * jj + 1]));
                sum0 += f0.x + f0.y;
                sum1 += f1.x + f1.y;
            }
            sum0 += __shfl_xor_sync(0xFFFFFFFFu, sum0, 1);
            sum0 += __shfl_xor_sync(0xFFFFFFFFu, sum0, 2);
            sum1 += __shfl_xor_sync(0xFFFFFFFFu, sum1, 1);
            sum1 += __shfl_xor_sync(0xFFFFFFFFu, sum1, 2);

            lr[i][0] = lr[i][0] * al0 + sum0;
            lr[i][1] = lr[i][1] * al1 + sum1;
            mr[i][0] = nm0; mr[i][1] = nm1;
#pragma unroll
            for (int j = 0; j < 8; j++) {
                o[i][j][0] *= al0; o[i][j][1] *= al0;
                o[i][j][2] *= al1; o[i][j][3] *= al1;
            }
        }

        // O += P V (V frags shared across m-tiles)
#pragma unroll
        for (int t = 0; t < 4; t++) {
#pragma unroll
            for (int jd = 0; jd < 4; jd++) {
                uint32_t v0, v1, v2, v3;
                int row = t * 16 + (lane & 15);
                int col = jd * 16 + ((lane >> 4) << 3);
                ldm_x4_t(v0, v1, v2, v3, sptr(&Vs[row * QST + col]));
#pragma unroll
                for (int i = 0; i < 2; i++) {
                    uint32_t a0 = *(const uint32_t*)&pl[i][2 * t];
                    uint32_t a1 = *(const uint32_t*)&ph[i][2 * t];
                    uint32_t a2 = *(const uint32_t*)&pl[i][2 * t + 1];
                    uint32_t a3 = *(const uint32_t*)&ph[i][2 * t + 1];
                    mma16816(o[i][2 * jd],     a0, a1, a2, a3, v0, v1);
                    mma16816(o[i][2 * jd + 1], a0, a1, a2, a3, v2, v3);
                }
            }
        }
    }

    // epilogue
#pragma unroll
    for (int i = 0; i < 2; i++) {
        float inv0 = 1.f / lr[i][0], inv1 = 1.f / lr[i][1];
        int nlow = qt * QROWS + i * 128 + w * 16 + (lane >> 2);
#pragma unroll
        for (int rh = 0; rh < 2; rh++) {
            int n = nlow + rh * 8;
            __half* drow = g_attout + (size_t)(b * N_ + n) * C_ + h * D_;
            float inv = rh ? inv1 : inv0;
#pragma unroll
            for (int j = 0; j < 8; j++) {
                int d = j * 8 + 2 * (lane & 3);
                *(__half2*)(drow + d) =
                    __floats2half2_rn(o[i][j][rh * 2 + 0] * inv, o[i][j][rh * 2 + 1] * inv);
            }
        }
    }
}

// ---------------------------------------------------------------------------
extern "C" void kernel_launch(void* const* d_in, const int* in_sizes, int n_in,
                              void* d_out, int out_size)
{
    const float* x   = (const float*)d_in[0];
    const float* wq  = (const float*)d_in[1];
    const float* bq  = (const float*)d_in[2];
    const float* wkv = (const float*)d_in[3];
    const float* bkv = (const float*)d_in[4];
    const float* wp  = (const float*)d_in[5];
    const float* bp  = (const float*)d_in[6];
    float* out = (float*)d_out;

    __half *xh, *wqkvT, *wpT, *attout;
    cudaGetSymbolAddress((void**)&xh,     g_xh);
    cudaGetSymbolAddress((void**)&wqkvT,  g_wqkvT);
    cudaGetSymbolAddress((void**)&wpT,    g_wpT);
    cudaGetSymbolAddress((void**)&attout, g_attout);

    cudaFuncSetAttribute(hgemm<0>, cudaFuncAttributeMaxDynamicSharedMemorySize, GEMM_SMEM);
    cudaFuncSetAttribute(hgemm<1>, cudaFuncAttributeMaxDynamicSharedMemorySize, GEMM_SMEM);
    cudaFuncSetAttribute(attn_kernel, cudaFuncAttributeMaxDynamicSharedMemorySize, ATTN_SMEM);

    f2h_kernel<<<(M_TOTAL * C_ / 4 + 255) / 256, 256>>>(x, xh, M_TOTAL * C_);
    transpose_all<<<dim3(2 * C_ / 32, C_ / 32, 3), dim3(32, 8)>>>(wq, wkv, wp);

    hgemm<0><<<dim3(M_TOTAL / 128, (3 * C_) / 128), 256, GEMM_SMEM>>>(xh, wqkvT, bq, bkv, nullptr);
    attn_kernel<<<dim3(N_ / QROWS, H_, B_), 256, ATTN_SMEM>>>();
    hgemm<1><<<dim3(M_TOTAL / 128, C_ / 128), 256, GEMM_SMEM>>>(attout, wpT, bp, nullptr, out);
}

// round 8
// speedup vs baseline: 9.8636x; 1.0220x over previous
#include <cuda_runtime.h>
#include <cuda_fp16.h>
#include <math_constants.h>
#include <cstdint>

#define B_  4
#define N_  2048
#define C_  768
#define H_  12
#define D_  64
#define M_TOTAL (B_ * N_)        // 8192

// ---------------------------------------------------------------------------
// Scratch (__device__ globals; allocation-free rule)
// ---------------------------------------------------------------------------
__device__ __half g_xh[M_TOTAL * C_];            // x in fp16 [8192][768]
__device__ __half g_wqkvT[3 * C_ * C_];          // [2304][768] rows: q|k|v, K-major
__device__ __half g_wpT[C_ * C_];                // [768][768]
__device__ __half g_q[B_ * H_ * N_ * D_];        // [B,H,N,D] fp16 (pre-scaled by 0.125*log2e)
__device__ __half g_k[B_ * H_ * N_ * D_];
__device__ __half g_v[B_ * H_ * N_ * D_];
__device__ __half g_attout[M_TOTAL * C_];        // [B,N,C] fp16

// ---------------------------------------------------------------------------
// helpers
// ---------------------------------------------------------------------------
__device__ __forceinline__ uint32_t sptr(const void* p) {
    return (uint32_t)__cvta_generic_to_shared(p);
}

__device__ __forceinline__ void cp16(uint32_t saddr, const void* g) {
    asm volatile("cp.async.cg.shared.global [%0], [%1], 16;"
                 :: "r"(saddr), "l"(__cvta_generic_to_global(g)));
}
#define CP_COMMIT() asm volatile("cp.async.commit_group;" ::: "memory")
#define CP_WAIT(n)  asm volatile("cp.async.wait_group %0;" :: "n"(n) : "memory")

__device__ __forceinline__ void ldm_x4(uint32_t& r0, uint32_t& r1, uint32_t& r2,
                                       uint32_t& r3, uint32_t addr) {
    asm volatile("ldmatrix.sync.aligned.m8n8.x4.shared.b16 {%0,%1,%2,%3}, [%4];"
                 : "=r"(r0), "=r"(r1), "=r"(r2), "=r"(r3) : "r"(addr));
}

__device__ __forceinline__ void ldm_x4_t(uint32_t& r0, uint32_t& r1, uint32_t& r2,
                                         uint32_t& r3, uint32_t addr) {
    asm volatile("ldmatrix.sync.aligned.m8n8.x4.trans.shared.b16 {%0,%1,%2,%3}, [%4];"
                 : "=r"(r0), "=r"(r1), "=r"(r2), "=r"(r3) : "r"(addr));
}

__device__ __forceinline__ void mma16816(float* c,
                                         uint32_t a0, uint32_t a1, uint32_t a2, uint32_t a3,
                                         uint32_t b0, uint32_t b1) {
    asm volatile(
        "mma.sync.aligned.m16n8k16.row.col.f32.f16.f16.f32 "
        "{%0,%1,%2,%3}, {%4,%5,%6,%7}, {%8,%9}, {%0,%1,%2,%3};"
        : "+f"(c[0]), "+f"(c[1]), "+f"(c[2]), "+f"(c[3])
        : "r"(a0), "r"(a1), "r"(a2), "r"(a3), "r"(b0), "r"(b1));
}

// half2 2^x (approx) — one MUFU per pair, fp16 result feeds mma directly
__device__ __forceinline__ __half2 hexp2_(__half2 x) {
    uint32_t r, xi = *(const uint32_t*)&x;
    asm("ex2.approx.f16x2 %0, %1;" : "=r"(r) : "r"(xi));
    return *(__half2*)&r;
}

// ---------------------------------------------------------------------------
// fp32 -> fp16 convert
// ---------------------------------------------------------------------------
__global__ void f2h_kernel(const float* __restrict__ src, __half* __restrict__ dst, int n)
{
    int i = (blockIdx.x * blockDim.x + threadIdx.x) * 4;
    if (i < n) {
        float4 v = *(const float4*)(src + i);
        *(__half2*)(dst + i)     = __floats2half2_rn(v.x, v.y);
        *(__half2*)(dst + i + 2) = __floats2half2_rn(v.z, v.w);
    }
}

// ---------------------------------------------------------------------------
// all-weights fp32 [K][N] -> fp16 [n][k] transpose in one launch
// ---------------------------------------------------------------------------
__global__ void transpose_all(const float* __restrict__ wq,
                              const float* __restrict__ wkv,
                              const float* __restrict__ wp)
{
    __shared__ float t[32][33];
    const int z = blockIdx.z;
    const float* src;
    __half* dst;
    int N;
    if (z == 0)      { src = wq;  dst = g_wqkvT;                     N = C_; }
    else if (z == 1) { src = wkv; dst = g_wqkvT + (size_t)C_ * C_;   N = 2 * C_; }
    else             { src = wp;  dst = g_wpT;                       N = C_; }
    if (blockIdx.x * 32 >= N) return;

    const int k0 = blockIdx.y * 32;
    const int n0 = blockIdx.x * 32;
    const int tx = threadIdx.x;
    const int ty = threadIdx.y;
#pragma unroll
    for (int i = ty; i < 32; i += 8)
        t[i][tx] = src[(size_t)(k0 + i) * N + n0 + tx];
    __syncthreads();
#pragma unroll
    for (int i = ty; i < 32; i += 8)
        dst[(size_t)(n0 + i) * C_ + k0 + tx] = __float2half(t[tx][i]);
}

// ---------------------------------------------------------------------------
// hgemm: C[128,128] = A[128xK] * Bt[128xK]^T (K=768), 3-stage cp.async ring.
// ---------------------------------------------------------------------------
#define AST 40
#define SSTRIDE (2 * 128 * AST)
#define GEMM_SMEM (3 * SSTRIDE * 2)             // 61440 bytes

__device__ __forceinline__ void hgemm_issue(uint32_t sb,
                                            const __half* Ab, const __half* Bb,
                                            int c, int r0c, int q0c)
{
    const int k0 = c * 32;
    const int s = c % 3;
    const uint32_t abase = sb + (uint32_t)(s * SSTRIDE) * 2;
    const uint32_t bbase = abase + 128 * AST * 2;
#pragma unroll
    for (int i = 0; i < 2; i++) {
        uint32_t so = (uint32_t)(r0c * AST + (q0c + i) * 8) * 2;
        cp16(abase + so, Ab + (size_t)r0c * C_ + k0 + (q0c + i) * 8);
        cp16(bbase + so, Bb + (size_t)r0c * C_ + k0 + (q0c + i) * 8);
    }
}

template <int MODE>
__global__ __launch_bounds__(256, 2) void hgemm(
    const __half* __restrict__ A, const __half* __restrict__ Bt,
    const float* __restrict__ bq, const float* __restrict__ bkv,
    float* __restrict__ outp)
{
    extern __shared__ __align__(16) __half sm[];
    const uint32_t sb = sptr(sm);

    const int tid = threadIdx.x;
    const int lane = tid & 31;
    const int wid = tid >> 5;
    const int wm = (wid >> 1) * 32;
    const int wn = (wid & 1) * 64;
    const int row0 = blockIdx.x * 128;
    const int n0   = blockIdx.y * 128;

    const __half* Ab = A  + (size_t)row0 * C_;
    const __half* Bb = Bt + (size_t)n0   * C_;

    const int r0c = (tid * 2) >> 2;
    const int q0c = (tid * 2) & 3;

    float acc[2][8][4];
#pragma unroll
    for (int i = 0; i < 2; i++)
#pragma unroll
        for (int j = 0; j < 8; j++)
#pragma unroll
            for (int q = 0; q < 4; q++) acc[i][j][q] = 0.f;

    hgemm_issue(sb, Ab, Bb, 0, r0c, q0c); CP_COMMIT();
    hgemm_issue(sb, Ab, Bb, 1, r0c, q0c); CP_COMMIT();

    for (int c = 0; c < 24; c++) {
        CP_WAIT(1);
        __syncthreads();
        if (c + 2 < 24) hgemm_issue(sb, Ab, Bb, c + 2, r0c, q0c);
        CP_COMMIT();

        const __half* Asb = sm + (c % 3) * SSTRIDE;
        const __half* Bsb = Asb + 128 * AST;
#pragma unroll
        for (int kk = 0; kk < 2; kk++) {
            uint32_t a[2][4];
#pragma unroll
            for (int i = 0; i < 2; i++) {
                int row = wm + i * 16 + (lane & 15);
                int col = kk * 16 + ((lane >> 4) << 3);
                ldm_x4(a[i][0], a[i][1], a[i][2], a[i][3],
                       sptr(&Asb[row * AST + col]));
            }
            uint32_t b[4][4];
#pragma unroll
            for (int p = 0; p < 4; p++) {
                int row = wn + p * 16 + ((lane >> 4) << 3) + (lane & 7);
                int col = kk * 16 + (((lane >> 3) & 1) << 3);
                ldm_x4(b[p][0], b[p][1], b[p][2], b[p][3],
                       sptr(&Bsb[row * AST + col]));
            }
#pragma unroll
            for (int i = 0; i < 2; i++)
#pragma unroll
                for (int j = 0; j < 8; j++) {
                    const uint32_t* bp = b[j >> 1];
                    mma16816(acc[i][j], a[i][0], a[i][1], a[i][2], a[i][3],
                             bp[(j & 1) * 2], bp[(j & 1) * 2 + 1]);
                }
        }
    }

    const int gcol0 = n0 + wn;
    if (MODE == 0) {
        const int sel = gcol0 / C_;
        const float* bias = (sel == 0) ? (bq + gcol0) : (bkv + gcol0 - C_);
        __half* dstb = (sel == 0) ? g_q : (sel == 1) ? g_k : g_v;
        const int h = (gcol0 % C_) / D_;
        // q pre-scale: D^-0.5 * log2(e) so attention can use exp2 directly
        const float qs = (sel == 0) ? 0.18033688011112042f : 1.0f;
#pragma unroll
        for (int i = 0; i < 2; i++) {
            int mlow = row0 + wm + i * 16 + (lane >> 2);
#pragma unroll
            for (int rh = 0; rh < 2; rh++) {
                int m = mlow + rh * 8;
                int bb = m >> 11;
                int nn = m & (N_ - 1);
                __half* drow = dstb + (size_t)((bb * H_ + h) * N_ + nn) * D_;
#pragma unroll
                for (int j = 0; j < 8; j++) {
                    int d = j * 8 + 2 * (lane & 3);
                    float2 bv = *(const float2*)(bias + d);
                    float v0 = (acc[i][j][rh * 2 + 0] + bv.x) * qs;
                    float v1 = (acc[i][j][rh * 2 + 1] + bv.y) * qs;
                    *(__half2*)(drow + d) = __floats2half2_rn(v0, v1);
                }
            }
        }
    } else {
#pragma unroll
        for (int i = 0; i < 2; i++) {
            int mlow = row0 + wm + i * 16 + (lane >> 2);
#pragma unroll
            for (int rh = 0; rh < 2; rh++) {
                int m = mlow + rh * 8;
                float* orow = outp + (size_t)m * C_ + gcol0;
#pragma unroll
                for (int j = 0; j < 8; j++) {
                    int d = j * 8 + 2 * (lane & 3);
                    float2 bv = *(const float2*)(bq + gcol0 + d);
                    float2 o;
                    o.x = acc[i][j][rh * 2 + 0] + bv.x;
                    o.y = acc[i][j][rh * 2 + 1] + bv.y;
                    *(float2*)(orow + d) = o;
                }
            }
        }
    }
}

// ---------------------------------------------------------------------------
// Flash attention v5: 128-thread CTAs (4 warps), 128 q rows/CTA, 2 m-tiles
// per warp (rows w*16 and w*16+64). 2 CTAs/SM for cross-CTA latency hiding.
// KV tiles of 64, cp.async double-buffered. Base-2 fp16 softmax.
// smem (halves): Qs[128*72] | stage{0,1}: Ks[64*72], Vs[64*72]
// ---------------------------------------------------------------------------
#define QST 72
#define QROWS 128
#define NTHR 128
#define QS_H   (QROWS * QST)                    // 9216 halves
#define KVST_H (2 * 64 * QST)                   // 9216 halves per stage
#define ATTN_SMEM ((QS_H + 2 * KVST_H) * 2)     // 55296 bytes

__device__ __forceinline__ void attn_issue_kv(uint32_t sb, const __half* kbase,
                                              const __half* vbase, int kt, int tid)
{
    const int s = kt & 1;
    const uint32_t kb0 = sb + (uint32_t)(QS_H + s * KVST_H) * 2;
    const uint32_t vb0 = kb0 + 64 * QST * 2;
    const __half* kg = kbase + (size_t)kt * 64 * D_;
    const __half* vg = vbase + (size_t)kt * 64 * D_;
#pragma unroll
    for (int i = 0; i < 4; i++) {
        int cch = tid + NTHR * i;       // 512 chunks (64 rows x 8)
        int r = cch >> 3, q = cch & 7;
        uint32_t so = (uint32_t)(r * QST + q * 8) * 2;
        cp16(kb0 + so, kg + (size_t)r * D_ + q * 8);
        cp16(vb0 + so, vg + (size_t)r * D_ + q * 8);
    }
}

__global__ __launch_bounds__(NTHR, 2) void attn_kernel()
{
    extern __shared__ __align__(16) __half sm[];
    const uint32_t sb = sptr(sm);

    const int qt = blockIdx.x;       // 16 tiles of 128 q rows
    const int h  = blockIdx.y;
    const int b  = blockIdx.z;
    const int tid = threadIdx.x;
    const int lane = tid & 31;
    const int w = tid >> 5;          // 0..3

    const __half* qbase = g_q + (size_t)((b * H_ + h) * N_ + qt * QROWS) * D_;
    const __half* kbase = g_k + (size_t)(b * H_ + h) * N_ * D_;
    const __half* vbase = g_v + (size_t)(b * H_ + h) * N_ * D_;

    // group 0: Q tile (128 rows x 8 chunks = 1024 chunks, 8/thread) + KV tile 0
#pragma unroll
    for (int i = 0; i < 8; i++) {
        int cch = tid + NTHR * i;
        int r = cch >> 3, q = cch & 7;
        cp16(sb + (uint32_t)(r * QST + q * 8) * 2, qbase + (size_t)r * D_ + q * 8);
    }
    attn_issue_kv(sb, kbase, vbase, 0, tid);
    CP_COMMIT();

    uint32_t qa[2][4][4];
    float mr[2][2], lr[2][2];
    float o[2][8][4];
#pragma unroll
    for (int i = 0; i < 2; i++) {
        mr[i][0] = -CUDART_INF_F; mr[i][1] = -CUDART_INF_F;
        lr[i][0] = 0.f; lr[i][1] = 0.f;
#pragma unroll
        for (int j = 0; j < 8; j++)
#pragma unroll
            for (int q = 0; q < 4; q++) o[i][j][q] = 0.f;
    }

    for (int kt = 0; kt < N_ / 64; kt++) {
        CP_WAIT(0);
        __syncthreads();
        if (kt == 0) {
#pragma unroll
            for (int i = 0; i < 2; i++)
#pragma unroll
                for (int kk = 0; kk < 4; kk++) {
                    int row = i * 64 + w * 16 + (lane & 15);
                    int col = kk * 16 + ((lane >> 4) << 3);
                    ldm_x4(qa[i][kk][0], qa[i][kk][1], qa[i][kk][2], qa[i][kk][3],
                           sptr(&sm[row * QST + col]));
                }
        }
        if (kt + 1 < N_ / 64) attn_issue_kv(sb, kbase, vbase, kt + 1, tid);
        CP_COMMIT();

        const __half* Ks = sm + QS_H + (kt & 1) * KVST_H;
        const __half* Vs = Ks + 64 * QST;

        // S = Q K^T (base-2 logits; scale folded into Q)
        float s[2][8][4];
#pragma unroll
        for (int i = 0; i < 2; i++)
#pragma unroll
            for (int j = 0; j < 8; j++)
#pragma unroll
                for (int q = 0; q < 4; q++) s[i][j][q] = 0.f;

#pragma unroll
        for (int kk = 0; kk < 4; kk++) {
            uint32_t kb[4][4];
#pragma unroll
            for (int p = 0; p < 4; p++) {
                int row = p * 16 + ((lane >> 4) << 3) + (lane & 7);
                int col = kk * 16 + (((lane >> 3) & 1) << 3);
                ldm_x4(kb[p][0], kb[p][1], kb[p][2], kb[p][3],
                       sptr(&Ks[row * QST + col]));
            }
#pragma unroll
            for (int i = 0; i < 2; i++)
#pragma unroll
                for (int j = 0; j < 8; j++) {
                    const uint32_t* bp = kb[j >> 1];
                    mma16816(s[i][j], qa[i][kk][0], qa[i][kk][1], qa[i][kk][2], qa[i][kk][3],
                             bp[(j & 1) * 2], bp[(j & 1) * 2 + 1]);
                }
        }

        // online softmax per m-tile (base 2, fp16 exponentials)
        __half2 pl[2][8], ph[2][8];
#pragma unroll
        for (int i = 0; i < 2; i++) {
            float mx0 = -CUDART_INF_F, mx1 = -CUDART_INF_F;
#pragma unroll
            for (int j = 0; j < 8; j++) {
                mx0 = fmaxf(mx0, fmaxf(s[i][j][0], s[i][j][1]));
                mx1 = fmaxf(mx1, fmaxf(s[i][j][2], s[i][j][3]));
            }
            mx0 = fmaxf(mx0, __shfl_xor_sync(0xFFFFFFFFu, mx0, 1));
            mx0 = fmaxf(mx0, __shfl_xor_sync(0xFFFFFFFFu, mx0, 2));
            mx1 = fmaxf(mx1, __shfl_xor_sync(0xFFFFFFFFu, mx1, 1));
            mx1 = fmaxf(mx1, __shfl_xor_sync(0xFFFFFFFFu, mx1, 2));

            float nm0 = fmaxf(mr[i][0], mx0), nm1 = fmaxf(mr[i][1], mx1);
            float al0 = exp2f(mr[i][0] - nm0), al1 = exp2f(mr[i][1] - nm1);
#pragma unroll
            for (int j = 0; j < 8; j++) {
                pl[i][j] = hexp2_(__floats2half2_rn(s[i][j][0] - nm0, s[i][j][1] - nm0));
                ph[i][j] = hexp2_(__floats2half2_rn(s[i][j][2] - nm1, s[i][j][3] - nm1));
            }
            // row sums of the quantized fp16 P (pairwise hadd2, fp32 accumulate)
            float sum0 = 0.f, sum1 = 0.f;
#pragma unroll
            for (int jj = 0; jj < 4; jj++) {
                float2 f0 = __half22float2(__hadd2(pl[i][2 * jj], pl[i][2 * jj + 1]));
                float2 f1 = __half22float2(__hadd2(ph[i][2 * jj], ph[i][2 * jj + 1]));
                sum0 += f0.x + f0.y;
                sum1 += f1.x + f1.y;
            }
            sum0 += __shfl_xor_sync(0xFFFFFFFFu, sum0, 1);
            sum0 += __shfl_xor_sync(0xFFFFFFFFu, sum0, 2);
            sum1 += __shfl_xor_sync(0xFFFFFFFFu, sum1, 1);
            sum1 += __shfl_xor_sync(0xFFFFFFFFu, sum1, 2);

            lr[i][0] = lr[i][0] * al0 + sum0;
            lr[i][1] = lr[i][1] * al1 + sum1;
            mr[i][0] = nm0; mr[i][1] = nm1;
#pragma unroll
            for (int j = 0; j < 8; j++) {
                o[i][j][0] *= al0; o[i][j][1] *= al0;
                o[i][j][2] *= al1; o[i][j][3] *= al1;
            }
        }

        // O += P V (V frags shared across m-tiles)
#pragma unroll
        for (int t = 0; t < 4; t++) {
#pragma unroll
            for (int jd = 0; jd < 4; jd++) {
                uint32_t v0, v1, v2, v3;
                int row = t * 16 + (lane & 15);
                int col = jd * 16 + ((lane >> 4) << 3);
                ldm_x4_t(v0, v1, v2, v3, sptr(&Vs[row * QST + col]));
#pragma unroll
                for (int i = 0; i < 2; i++) {
                    uint32_t a0 = *(const uint32_t*)&pl[i][2 * t];
                    uint32_t a1 = *(const uint32_t*)&ph[i][2 * t];
                    uint32_t a2 = *(const uint32_t*)&pl[i][2 * t + 1];
                    uint32_t a3 = *(const uint32_t*)&ph[i][2 * t + 1];
                    mma16816(o[i][2 * jd],     a0, a1, a2, a3, v0, v1);
                    mma16816(o[i][2 * jd + 1], a0, a1, a2, a3, v2, v3);
                }
            }
        }
    }

    // epilogue
#pragma unroll
    for (int i = 0; i < 2; i++) {
        float inv0 = 1.f / lr[i][0], inv1 = 1.f / lr[i][1];
        int nlow = qt * QROWS + i * 64 + w * 16 + (lane >> 2);
#pragma unroll
        for (int rh = 0; rh < 2; rh++) {
            int n = nlow + rh * 8;
            __half* drow = g_attout + (size_t)(b * N_ + n) * C_ + h * D_;
            float inv = rh ? inv1 : inv0;
#pragma unroll
            for (int j = 0; j < 8; j++) {
                int d = j * 8 + 2 * (lane & 3);
                *(__half2*)(drow + d) =
                    __floats2half2_rn(o[i][j][rh * 2 + 0] * inv, o[i][j][rh * 2 + 1] * inv);
            }
        }
    }
}

// ---------------------------------------------------------------------------
extern "C" void kernel_launch(void* const* d_in, const int* in_sizes, int n_in,
                              void* d_out, int out_size)
{
    const float* x   = (const float*)d_in[0];
    const float* wq  = (const float*)d_in[1];
    const float* bq  = (const float*)d_in[2];
    const float* wkv = (const float*)d_in[3];
    const float* bkv = (const float*)d_in[4];
    const float* wp  = (const float*)d_in[5];
    const float* bp  = (const float*)d_in[6];
    float* out = (float*)d_out;

    __half *xh, *wqkvT, *wpT, *attout;
    cudaGetSymbolAddress((void**)&xh,     g_xh);
    cudaGetSymbolAddress((void**)&wqkvT,  g_wqkvT);
    cudaGetSymbolAddress((void**)&wpT,    g_wpT);
    cudaGetSymbolAddress((void**)&attout, g_attout);

    cudaFuncSetAttribute(hgemm<0>, cudaFuncAttributeMaxDynamicSharedMemorySize, GEMM_SMEM);
    cudaFuncSetAttribute(hgemm<1>, cudaFuncAttributeMaxDynamicSharedMemorySize, GEMM_SMEM);
    cudaFuncSetAttribute(attn_kernel, cudaFuncAttributeMaxDynamicSharedMemorySize, ATTN_SMEM);

    f2h_kernel<<<(M_TOTAL * C_ / 4 + 255) / 256, 256>>>(x, xh, M_TOTAL * C_);
    transpose_all<<<dim3(2 * C_ / 32, C_ / 32, 3), dim3(32, 8)>>>(wq, wkv, wp);

    hgemm<0><<<dim3(M_TOTAL / 128, (3 * C_) / 128), 256, GEMM_SMEM>>>(xh, wqkvT, bq, bkv, nullptr);
    attn_kernel<<<dim3(N_ / QROWS, H_, B_), NTHR, ATTN_SMEM>>>();
    hgemm<1><<<dim3(M_TOTAL / 128, C_ / 128), 256, GEMM_SMEM>>>(attout, wpT, bp, nullptr, out);
}